// round 14
// baseline (speedup 1.0000x reference)
#include <cuda_runtime.h>
#include <cuda_bf16.h>
#include <cstdint>

// ---------------------------------------------------------------------------
// MoEEncoderLayer: B=2 L=2048 D=512 H=8 E=8 K=2 DF=2048
// Output layout in d_out (float32): [out: T*D][attn: B*H*L*L][aug_loss: 1]
// bf16x3 split-precision mma.sync m16n8k16; operands pre-split into bf16
// hi/lo planes; GEMM mainloop = cp.async + ldmatrix + mma.
// This round: NS=5 pipeline (wait<3>) on gemm_s/expert_s/attnv_s for more
// load-latency tolerance; scores stays NS=4. Streams as in R13.
// ---------------------------------------------------------------------------

#define Bb 2
#define Ls 2048
#define Dm 512
#define Hh 8
#define Ee 8
#define KTOP 2
#define Fd 2048
#define Hd 64
#define Tt (Bb*Ls)                      // 4096
#define NS 4                            // stages for scores (k16, 4 iters)
#define NSG 5                           // stages for big-K kernels

static const long long ATTN_OFF = (long long)Tt * Dm;                      // 2097152
static const long long LOSS_OFF = ATTN_OFF + (long long)Bb*Hh*Ls*Ls;       // 69206016

// ------------------------- scratch (device globals) ------------------------
__device__ float g_v[Tt*Dm];
__device__ float g_tmp[Tt*Dm];
__device__ float g_x1[Tt*Dm];
__device__ float g_gh[Tt*Dm];
__device__ float g_logits[Tt*Ee];
__device__ float g_wk[Tt*KTOP];
__device__ int   g_cnt[Ee];
__device__ int   g_list[Ee*Tt];
__device__ float g_y[Tt*KTOP*Dm];
__device__ float g_gen[Tt*Dm];

// split planes (bf16 bits as ushort)
__device__ unsigned short s_xh[Tt*Dm],   s_xl[Tt*Dm];
__device__ unsigned short s_qh[Tt*Dm],   s_ql[Tt*Dm];
__device__ unsigned short s_kh[Tt*Dm],   s_kl[Tt*Dm];
__device__ unsigned short s_vth[Tt*Dm],  s_vtl[Tt*Dm];     // vT [Bb][Dm][Ls]
__device__ unsigned short s_ctxh[Tt*Dm], s_ctxl[Tt*Dm];
__device__ unsigned short s_x1h[Tt*Dm],  s_x1l[Tt*Dm];
__device__ unsigned short s_ehh[Tt*KTOP*Fd], s_ehl[Tt*KTOP*Fd];
__device__ unsigned short s_gnh[Tt*Fd],  s_gnl[Tt*Fd];
__device__ unsigned short s_ph[(long long)Bb*Hh*Ls*Ls];
__device__ unsigned short s_pl[(long long)Bb*Hh*Ls*Ls];
// weight planes, transposed to [N x K]
__device__ unsigned short s_wqh[Dm*Dm], s_wql[Dm*Dm];
__device__ unsigned short s_wkh[Dm*Dm], s_wkl[Dm*Dm];
__device__ unsigned short s_wvh[Dm*Dm], s_wvl[Dm*Dm];
__device__ unsigned short s_woh[Dm*Dm], s_wol[Dm*Dm];
__device__ unsigned short s_gw1h[Dm*Dm], s_gw1l[Dm*Dm];
__device__ unsigned short s_gew1h[Fd*Dm], s_gew1l[Fd*Dm];
__device__ unsigned short s_gew2h[Dm*Fd], s_gew2l[Dm*Fd];
__device__ unsigned short s_ew1h[Ee*Fd*Dm], s_ew1l[Ee*Fd*Dm];
__device__ unsigned short s_ew2h[Ee*Dm*Fd], s_ew2l[Ee*Dm*Fd];

// ------------------------------- helpers -----------------------------------
__device__ __forceinline__ float gelu_tanh(float x) {
    float x3 = x * x * x;
    float t  = tanhf(0.7978845608028654f * (x + 0.044715f * x3));
    return 0.5f * x * (1.0f + t);
}
__device__ __forceinline__ void bsplit(float x, unsigned short& h, unsigned short& l) {
    __nv_bfloat16 hb = __float2bfloat16_rn(x);
    float hf = __bfloat162float(hb);
    __nv_bfloat16 lb = __float2bfloat16_rn(x - hf);
    h = __bfloat16_as_ushort(hb);
    l = __bfloat16_as_ushort(lb);
}
__device__ __forceinline__ void bsplit2(float x0, float x1, uint32_t& hp, uint32_t& lp) {
    unsigned short h0, l0, h1, l1;
    bsplit(x0, h0, l0);
    bsplit(x1, h1, l1);
    hp = (uint32_t)h0 | ((uint32_t)h1 << 16);
    lp = (uint32_t)l0 | ((uint32_t)l1 << 16);
}
__device__ __forceinline__ void mma16(float* c, const uint32_t* a, const uint32_t* b) {
    asm volatile(
        "mma.sync.aligned.m16n8k16.row.col.f32.bf16.bf16.f32 "
        "{%0,%1,%2,%3}, {%4,%5,%6,%7}, {%8,%9}, {%0,%1,%2,%3};"
        : "+f"(c[0]), "+f"(c[1]), "+f"(c[2]), "+f"(c[3])
        : "r"(a[0]), "r"(a[1]), "r"(a[2]), "r"(a[3]), "r"(b[0]), "r"(b[1]));
}
__device__ __forceinline__ void ldsm4(uint32_t* d, uint32_t addr) {
    asm volatile("ldmatrix.sync.aligned.m8n8.x4.shared.b16 {%0,%1,%2,%3}, [%4];"
        : "=r"(d[0]), "=r"(d[1]), "=r"(d[2]), "=r"(d[3]) : "r"(addr));
}
__device__ __forceinline__ void cpa16(uint32_t dst, const void* src, bool pred) {
    int sz = pred ? 16 : 0;
    asm volatile("cp.async.cg.shared.global [%0], [%1], 16, %2;\n"
        :: "r"(dst), "l"(src), "r"(sz));
}
__device__ __forceinline__ void cpa_commit() { asm volatile("cp.async.commit_group;"); }
template<int N> __device__ __forceinline__ void cpa_wait() {
    asm volatile("cp.async.wait_group %0;" :: "n"(N));
}
__device__ __forceinline__ int swz8(int row, int khalf) {
    return row * 16 + ((khalf ^ ((row >> 2) & 1)) << 3);
}

__device__ __forceinline__ float warpReduceSum(float v) {
    #pragma unroll
    for (int o = 16; o > 0; o >>= 1) v += __shfl_xor_sync(0xffffffffu, v, o);
    return v;
}
__device__ __forceinline__ float warpReduceMax(float v) {
    #pragma unroll
    for (int o = 16; o > 0; o >>= 1) v = fmaxf(v, __shfl_xor_sync(0xffffffffu, v, o));
    return v;
}
__device__ __forceinline__ float blockReduceSum256(float v) {
    __shared__ float sh[33];
    int tid = threadIdx.x, lane = tid & 31, wid = tid >> 5;
    v = warpReduceSum(v);
    if (lane == 0) sh[wid] = v;
    __syncthreads();
    if (tid < 8) {
        float x = sh[tid];
        #pragma unroll
        for (int o = 4; o > 0; o >>= 1) x += __shfl_xor_sync(0xffu, x, o);
        if (tid == 0) sh[32] = x;
    }
    __syncthreads();
    float r = sh[32];
    __syncthreads();
    return r;
}
__device__ __forceinline__ float blockReduceMax256(float v) {
    __shared__ float sh[33];
    int tid = threadIdx.x, lane = tid & 31, wid = tid >> 5;
    v = warpReduceMax(v);
    if (lane == 0) sh[wid] = v;
    __syncthreads();
    if (tid < 8) {
        float x = sh[tid];
        #pragma unroll
        for (int o = 4; o > 0; o >>= 1) x = fmaxf(x, __shfl_xor_sync(0xffu, x, o));
        if (tid == 0) sh[32] = x;
    }
    __syncthreads();
    float r = sh[32];
    __syncthreads();
    return r;
}

#define SPLIT_MMA(ACC0, ACC1, AH, AL, BH, BL)                             \
    mma16(ACC0, AH[0], BH); mma16(ACC1, AH[1], BH);                        \
    mma16(ACC0, AL[0], BH); mma16(ACC1, AL[1], BH);                        \
    mma16(ACC0, AH[0], BL); mma16(ACC1, AH[1], BL);

// ======================= conversion kernels ================================
__global__ void __launch_bounds__(256)
esplit_kernel(const float* __restrict__ in, unsigned short* __restrict__ oh,
              unsigned short* __restrict__ ol, int n)
{
    int i = blockIdx.x * 256 + threadIdx.x;
    if (i < n) {
        unsigned short h, l;
        bsplit(in[i], h, l);
        oh[i] = h; ol[i] = l;
    }
}

// in [K x N] fp32 (batched) -> planes [N x K] bf16 hi/lo (batched)
__global__ void __launch_bounds__(256)
wsplit_t_kernel(const float* __restrict__ in, unsigned short* __restrict__ oh,
                unsigned short* __restrict__ ol, int K, int N)
{
    __shared__ float t[32][33];
    long long base = (long long)blockIdx.z * K * N;
    int n0 = blockIdx.x * 32, k0 = blockIdx.y * 32;
    int tx = threadIdx.x & 31, ty = threadIdx.x >> 5;   // (32, 8)
    #pragma unroll
    for (int i = 0; i < 4; i++)
        t[ty + i*8][tx] = in[base + (long long)(k0 + ty + i*8) * N + n0 + tx];
    __syncthreads();
    #pragma unroll
    for (int i = 0; i < 4; i++) {
        unsigned short h, l;
        bsplit(t[tx][ty + i*8], h, l);
        long long o = base + (long long)(n0 + ty + i*8) * K + k0 + tx;
        oh[o] = h; ol[o] = l;
    }
}

// ===================== generic GEMM (pre-split planes, NSG=5) ===============
// C = act(A @ W + bias); A planes [M x Kd]; B planes [N x Kd] (pre-transposed)
// OMODE: 0 = fp32 C, 1 = split planes C
template<int ACT, int OMODE>
__global__ void __launch_bounds__(256)
gemm_s(const unsigned short* __restrict__ Ahi, const unsigned short* __restrict__ Alo,
       const unsigned short* __restrict__ Bhi, const unsigned short* __restrict__ Blo,
       const float* __restrict__ bias, float* __restrict__ Cf,
       unsigned short* __restrict__ Chi, unsigned short* __restrict__ Clo,
       int N, int Kd)
{
    extern __shared__ unsigned short sm[];
    unsigned short* As_hi = sm;
    unsigned short* As_lo = sm + NSG*2048;
    unsigned short* Bs_hi = sm + 2*NSG*2048;
    unsigned short* Bs_lo = sm + 3*NSG*2048;

    const int tid = threadIdx.x, lane = tid & 31, wid = tid >> 5;
    const int g = lane >> 2, tg = lane & 3;
    const int wm = (wid & 3) * 32, wn = (wid >> 2) * 64;
    const int m0 = blockIdx.y * 128, n0 = blockIdx.x * 128;

    const int lm = tid >> 1, lkh = tid & 1;
    const int aso = swz8(lm, lkh);

    const unsigned short* Ah = Ahi + (long long)(m0 + lm) * Kd + lkh * 8;
    const unsigned short* Al = Alo + (long long)(m0 + lm) * Kd + lkh * 8;
    const unsigned short* Bh = Bhi + (long long)(n0 + lm) * Kd + lkh * 8;
    const unsigned short* Bl = Blo + (long long)(n0 + lm) * Kd + lkh * 8;

    const uint32_t aHiS = (uint32_t)__cvta_generic_to_shared(As_hi) + aso*2;
    const uint32_t aLoS = (uint32_t)__cvta_generic_to_shared(As_lo) + aso*2;
    const uint32_t bHiS = (uint32_t)__cvta_generic_to_shared(Bs_hi) + aso*2;
    const uint32_t bLoS = (uint32_t)__cvta_generic_to_shared(Bs_lo) + aso*2;

    const int rA = wm + ((lane >> 3) & 1) * 8 + (lane & 7);
    const uint32_t aOff = (uint32_t)(swz8(rA, (lane >> 4) & 1) * 2);
    const int cB = wn + ((lane >> 4) & 1) * 8 + (lane & 7);
    const uint32_t bOff = (uint32_t)(swz8(cB, (lane >> 3) & 1) * 2);
    const uint32_t aHiB = (uint32_t)__cvta_generic_to_shared(As_hi) + aOff;
    const uint32_t aLoB = (uint32_t)__cvta_generic_to_shared(As_lo) + aOff;
    const uint32_t bHiB = (uint32_t)__cvta_generic_to_shared(Bs_hi) + bOff;
    const uint32_t bLoB = (uint32_t)__cvta_generic_to_shared(Bs_lo) + bOff;

    float acc[2][8][4];
    #pragma unroll
    for (int i = 0; i < 2; i++)
        #pragma unroll
        for (int j = 0; j < 8; j++)
            #pragma unroll
            for (int q = 0; q < 4; q++) acc[i][j][q] = 0.f;

    const int nit = Kd / 16;   // >= 32 for all uses
    #define G_ISSUE(s, k0v) { uint32_t o = (uint32_t)(s)*4096;              \
        cpa16(aHiS + o, Ah + (k0v), true); cpa16(aLoS + o, Al + (k0v), true);\
        cpa16(bHiS + o, Bh + (k0v), true); cpa16(bLoS + o, Bl + (k0v), true);\
        cpa_commit(); }

    #pragma unroll
    for (int s = 0; s < NSG-1; s++) if (s < nit) G_ISSUE(s, s*16);

    int slot = 0, isl = NSG - 1;
    for (int it = 0; it < nit; it++) {
        cpa_wait<NSG-2>();
        __syncthreads();
        const uint32_t st = (uint32_t)slot * 4096;
        uint32_t ah[2][4], al[2][4];
        ldsm4(ah[0], aHiB + st);  ldsm4(ah[1], aHiB + st + 512);
        ldsm4(al[0], aLoB + st);  ldsm4(al[1], aLoB + st + 512);
        #pragma unroll
        for (int p = 0; p < 4; p++) {
            uint32_t bh[4], bl[4];
            ldsm4(bh, bHiB + st + p * 512);
            ldsm4(bl, bLoB + st + p * 512);
            SPLIT_MMA(acc[0][2*p],   acc[1][2*p],   ah, al, (bh + 0), (bl + 0));
            SPLIT_MMA(acc[0][2*p+1], acc[1][2*p+1], ah, al, (bh + 2), (bl + 2));
        }
        int nxt = it + NSG - 1;
        if (nxt < nit) { G_ISSUE(isl, nxt*16); } else { cpa_commit(); }
        slot = (slot + 1 == NSG) ? 0 : slot + 1;
        isl  = (isl  + 1 == NSG) ? 0 : isl  + 1;
    }
    #undef G_ISSUE

    #pragma unroll
    for (int mi = 0; mi < 2; mi++) {
        const int r0 = m0 + wm + mi * 16 + g;
        #pragma unroll
        for (int nj = 0; nj < 8; nj++) {
            const int c = n0 + wn + nj * 8 + tg * 2;
            const float b0v = bias[c], b1v = bias[c + 1];
            float v0 = acc[mi][nj][0] + b0v, v1 = acc[mi][nj][1] + b1v;
            float v2 = acc[mi][nj][2] + b0v, v3 = acc[mi][nj][3] + b1v;
            if (ACT) { v0 = gelu_tanh(v0); v1 = gelu_tanh(v1); v2 = gelu_tanh(v2); v3 = gelu_tanh(v3); }
            if (OMODE == 0) {
                *(float2*)&Cf[(long long)r0 * N + c]       = make_float2(v0, v1);
                *(float2*)&Cf[(long long)(r0 + 8) * N + c] = make_float2(v2, v3);
            } else {
                uint32_t hp, lp;
                bsplit2(v0, v1, hp, lp);
                *(uint32_t*)&Chi[(long long)r0 * N + c] = hp;
                *(uint32_t*)&Clo[(long long)r0 * N + c] = lp;
                bsplit2(v2, v3, hp, lp);
                *(uint32_t*)&Chi[(long long)(r0 + 8) * N + c] = hp;
                *(uint32_t*)&Clo[(long long)(r0 + 8) * N + c] = lp;
            }
        }
    }
}

// ==================  gathered expert GEMMs (batched, e-offset, NSG=5) =======
// MODE 0: eh[ent] = gelu(x1[ent>>1] @ eW1[e] + eb1[e])   (N=Fd, Kd=Dm)
// MODE 1: y[ent]  = eh[ent] @ eW2[e] + eb2[e]            (N=Dm, Kd=Fd)
template<int MODE>
__global__ void __launch_bounds__(256)
expert_s(const unsigned short* __restrict__ Whi, const unsigned short* __restrict__ Wlo,
         const float* __restrict__ bias, const int e0)
{
    const int e = e0 + blockIdx.z;
    const int cnt = g_cnt[e];
    const int r0blk = blockIdx.y * 128;
    if (r0blk >= cnt) return;

    const int N  = MODE ? Dm : Fd;
    const int Kd = MODE ? Fd : Dm;

    extern __shared__ unsigned short sm[];
    unsigned short* As_hi = sm;
    unsigned short* As_lo = sm + NSG*2048;
    unsigned short* Bs_hi = sm + 2*NSG*2048;
    unsigned short* Bs_lo = sm + 3*NSG*2048;
    __shared__ int toks[128];

    const int tid = threadIdx.x, lane = tid & 31, wid = tid >> 5;
    const int g = lane >> 2, tg = lane & 3;
    const int wm = (wid & 3) * 32, wn = (wid >> 2) * 64;
    const int n0 = blockIdx.x * 128;

    if (tid < 128) {
        int r = r0blk + tid;
        toks[tid] = (r < cnt) ? g_list[e * Tt + r] : -1;
    }
    __syncthreads();

    const int lm = tid >> 1, lkh = tid & 1;
    const int aso = swz8(lm, lkh);

    const int entA = toks[lm];
    const bool apred = (entA >= 0);
    long long arow = apred ? (MODE ? (long long)entA : (long long)(entA >> 1)) : 0;
    const unsigned short* Ahp = (MODE ? s_ehh : s_x1h) + arow * Kd + lkh * 8;
    const unsigned short* Alp = (MODE ? s_ehl : s_x1l) + arow * Kd + lkh * 8;
    const unsigned short* Bhp = Whi + (long long)e * Dm * Fd + (long long)(n0 + lm) * Kd + lkh * 8;
    const unsigned short* Blp = Wlo + (long long)e * Dm * Fd + (long long)(n0 + lm) * Kd + lkh * 8;
    const float* bp = bias + (long long)e * N;

    const uint32_t aHiS = (uint32_t)__cvta_generic_to_shared(As_hi) + aso*2;
    const uint32_t aLoS = (uint32_t)__cvta_generic_to_shared(As_lo) + aso*2;
    const uint32_t bHiS = (uint32_t)__cvta_generic_to_shared(Bs_hi) + aso*2;
    const uint32_t bLoS = (uint32_t)__cvta_generic_to_shared(Bs_lo) + aso*2;

    const int rA = wm + ((lane >> 3) & 1) * 8 + (lane & 7);
    const uint32_t aOff = (uint32_t)(swz8(rA, (lane >> 4) & 1) * 2);
    const int cB = wn + ((lane >> 4) & 1) * 8 + (lane & 7);
    const uint32_t bOff = (uint32_t)(swz8(cB, (lane >> 3) & 1) * 2);
    const uint32_t aHiB = (uint32_t)__cvta_generic_to_shared(As_hi) + aOff;
    const uint32_t aLoB = (uint32_t)__cvta_generic_to_shared(As_lo) + aOff;
    const uint32_t bHiB = (uint32_t)__cvta_generic_to_shared(Bs_hi) + bOff;
    const uint32_t bLoB = (uint32_t)__cvta_generic_to_shared(Bs_lo) + bOff;

    float acc[2][8][4];
    #pragma unroll
    for (int i = 0; i < 2; i++)
        #pragma unroll
        for (int j = 0; j < 8; j++)
            #pragma unroll
            for (int q = 0; q < 4; q++) acc[i][j][q] = 0.f;

    const int nit = Kd / 16;
    #define E_ISSUE(s, k0v) { uint32_t o = (uint32_t)(s)*4096;                 \
        cpa16(aHiS + o, Ahp + (k0v), apred); cpa16(aLoS + o, Alp + (k0v), apred);\
        cpa16(bHiS + o, Bhp + (k0v), true);  cpa16(bLoS + o, Blp + (k0v), true); \
        cpa_commit(); }

    #pragma unroll
    for (int s = 0; s < NSG-1; s++) if (s < nit) E_ISSUE(s, s*16);

    int slot = 0, isl = NSG - 1;
    for (int it = 0; it < nit; it++) {
        cpa_wait<NSG-2>();
        __syncthreads();
        const uint32_t st = (uint32_t)slot * 4096;
        uint32_t ah[2][4], al[2][4];
        ldsm4(ah[0], aHiB + st);  ldsm4(ah[1], aHiB + st + 512);
        ldsm4(al[0], aLoB + st);  ldsm4(al[1], aLoB + st + 512);
        #pragma unroll
        for (int p = 0; p < 4; p++) {
            uint32_t bh[4], bl[4];
            ldsm4(bh, bHiB + st + p * 512);
            ldsm4(bl, bLoB + st + p * 512);
            SPLIT_MMA(acc[0][2*p],   acc[1][2*p],   ah, al, (bh + 0), (bl + 0));
            SPLIT_MMA(acc[0][2*p+1], acc[1][2*p+1], ah, al, (bh + 2), (bl + 2));
        }
        int nxt = it + NSG - 1;
        if (nxt < nit) { E_ISSUE(isl, nxt*16); } else { cpa_commit(); }
        slot = (slot + 1 == NSG) ? 0 : slot + 1;
        isl  = (isl  + 1 == NSG) ? 0 : isl  + 1;
    }
    #undef E_ISSUE

    #pragma unroll
    for (int mi = 0; mi < 2; mi++) {
        const int rr0 = wm + mi * 16 + g;
        const int ent0 = toks[rr0], ent1 = toks[rr0 + 8];
        #pragma unroll
        for (int nj = 0; nj < 8; nj++) {
            const int c = wn + nj * 8 + tg * 2;
            const float b0v = bp[n0 + c], b1v = bp[n0 + c + 1];
            if (ent0 >= 0) {
                float v0 = acc[mi][nj][0] + b0v, v1 = acc[mi][nj][1] + b1v;
                if (MODE == 0) {
                    v0 = gelu_tanh(v0); v1 = gelu_tanh(v1);
                    uint32_t hp, lp;
                    bsplit2(v0, v1, hp, lp);
                    *(uint32_t*)&s_ehh[(long long)ent0 * Fd + n0 + c] = hp;
                    *(uint32_t*)&s_ehl[(long long)ent0 * Fd + n0 + c] = lp;
                } else {
                    *(float2*)&g_y[(long long)ent0 * Dm + n0 + c] = make_float2(v0, v1);
                }
            }
            if (ent1 >= 0) {
                float v2 = acc[mi][nj][2] + b0v, v3 = acc[mi][nj][3] + b1v;
                if (MODE == 0) {
                    v2 = gelu_tanh(v2); v3 = gelu_tanh(v3);
                    uint32_t hp, lp;
                    bsplit2(v2, v3, hp, lp);
                    *(uint32_t*)&s_ehh[(long long)ent1 * Fd + n0 + c] = hp;
                    *(uint32_t*)&s_ehl[(long long)ent1 * Fd + n0 + c] = lp;
                } else {
                    *(float2*)&g_y[(long long)ent1 * Dm + n0 + c] = make_float2(v2, v3);
                }
            }
        }
    }
}

// ================  attention scores: Q K^T / 8  (NS=4, unchanged) ==========
__global__ void __launch_bounds__(256)
scores_s(float* __restrict__ attn)
{
    extern __shared__ unsigned short sm[];
    unsigned short* As_hi = sm;
    unsigned short* As_lo = sm + NS*2048;
    unsigned short* Bs_hi = sm + 2*NS*2048;
    unsigned short* Bs_lo = sm + 3*NS*2048;

    const int tid = threadIdx.x, lane = tid & 31, wid = tid >> 5;
    const int g = lane >> 2, tg = lane & 3;
    const int wm = (wid & 3) * 32, wn = (wid >> 2) * 64;
    const int bh_ = blockIdx.z; const int b = bh_ >> 3, h = bh_ & 7;
    const int i0 = blockIdx.y * 128, j0 = blockIdx.x * 128;

    const int lm = tid >> 1, lkh = tid & 1;
    const int aso = swz8(lm, lkh);

    const unsigned short* Ah = s_qh + (long long)(b*Ls + i0 + lm) * Dm + h*Hd + lkh*8;
    const unsigned short* Al = s_ql + (long long)(b*Ls + i0 + lm) * Dm + h*Hd + lkh*8;
    const unsigned short* Bh = s_kh + (long long)(b*Ls + j0 + lm) * Dm + h*Hd + lkh*8;
    const unsigned short* Bl = s_kl + (long long)(b*Ls + j0 + lm) * Dm + h*Hd + lkh*8;

    const uint32_t aHiS = (uint32_t)__cvta_generic_to_shared(As_hi) + aso*2;
    const uint32_t aLoS = (uint32_t)__cvta_generic_to_shared(As_lo) + aso*2;
    const uint32_t bHiS = (uint32_t)__cvta_generic_to_shared(Bs_hi) + aso*2;
    const uint32_t bLoS = (uint32_t)__cvta_generic_to_shared(Bs_lo) + aso*2;

    const int rA = wm + ((lane >> 3) & 1) * 8 + (lane & 7);
    const uint32_t aOff = (uint32_t)(swz8(rA, (lane >> 4) & 1) * 2);
    const int cB = wn + ((lane >> 4) & 1) * 8 + (lane & 7);
    const uint32_t bOff = (uint32_t)(swz8(cB, (lane >> 3) & 1) * 2);
    const uint32_t aHiB = (uint32_t)__cvta_generic_to_shared(As_hi) + aOff;
    const uint32_t aLoB = (uint32_t)__cvta_generic_to_shared(As_lo) + aOff;
    const uint32_t bHiB = (uint32_t)__cvta_generic_to_shared(Bs_hi) + bOff;
    const uint32_t bLoB = (uint32_t)__cvta_generic_to_shared(Bs_lo) + bOff;

    float acc[2][8][4];
    #pragma unroll
    for (int i = 0; i < 2; i++)
        #pragma unroll
        for (int j = 0; j < 8; j++)
            #pragma unroll
            for (int q2 = 0; q2 < 4; q2++) acc[i][j][q2] = 0.f;

    const int nit = Hd / 16;   // 4
    #define S_ISSUE(s, k0v) { uint32_t o = (uint32_t)(s)*4096;              \
        cpa16(aHiS + o, Ah + (k0v), true); cpa16(aLoS + o, Al + (k0v), true);\
        cpa16(bHiS + o, Bh + (k0v), true); cpa16(bLoS + o, Bl + (k0v), true);\
        cpa_commit(); }

    #pragma unroll
    for (int s = 0; s < NS-1; s++) if (s < nit) S_ISSUE(s, s*16);

    for (int it = 0; it < nit; it++) {
        cpa_wait<NS-2>();
        __syncthreads();
        const uint32_t st = (uint32_t)(it & (NS-1)) * 4096;
        uint32_t ah[2][4], al[2][4];
        ldsm4(ah[0], aHiB + st);  ldsm4(ah[1], aHiB + st + 512);
        ldsm4(al[0], aLoB + st);  ldsm4(al[1], aLoB + st + 512);
        #pragma unroll
        for (int p = 0; p < 4; p++) {
            uint32_t bh2[4], bl2[4];
            ldsm4(bh2, bHiB + st + p * 512);
            ldsm4(bl2, bLoB + st + p * 512);
            SPLIT_MMA(acc[0][2*p],   acc[1][2*p],   ah, al, (bh2 + 0), (bl2 + 0));
            SPLIT_MMA(acc[0][2*p+1], acc[1][2*p+1], ah, al, (bh2 + 2), (bl2 + 2));
        }
        int nxt = it + NS - 1;
        if (nxt < nit) { S_ISSUE(nxt & (NS-1), nxt*16); } else { cpa_commit(); }
    }
    #undef S_ISSUE

    float* O = attn + (long long)bh_ * Ls * Ls;
    #pragma unroll
    for (int mi = 0; mi < 2; mi++) {
        const int r0 = i0 + wm + mi * 16 + g;
        #pragma unroll
        for (int nj = 0; nj < 8; nj++) {
            const int c = j0 + wn + nj * 8 + tg * 2;
            *(float2*)&O[(long long)r0 * Ls + c] =
                make_float2(acc[mi][nj][0] * 0.125f, acc[mi][nj][1] * 0.125f);
            *(float2*)&O[(long long)(r0 + 8) * Ls + c] =
                make_float2(acc[mi][nj][2] * 0.125f, acc[mi][nj][3] * 0.125f);
        }
    }
}

// =====================  P @ V  (NSG=5) ======================================
// grid = (1, L/128, B*H).  Block 128x64, warp 32x32, Kd = L = 2048.
__global__ void __launch_bounds__(256)
attnv_s()
{
    extern __shared__ unsigned short sm[];
    unsigned short* As_hi = sm;                 // NSG*2048
    unsigned short* As_lo = sm + NSG*2048;
    unsigned short* Bs_hi = sm + 2*NSG*2048;    // NSG*1024
    unsigned short* Bs_lo = sm + 2*NSG*2048 + NSG*1024;

    const int tid = threadIdx.x, lane = tid & 31, wid = tid >> 5;
    const int g = lane >> 2, tg = lane & 3;
    const int wm = (wid & 3) * 32, wn = (wid >> 2) * 32;
    const int bh_ = blockIdx.z; const int b = bh_ >> 3, h = bh_ & 7;
    const int i0 = blockIdx.y * 128;

    const int lm = tid >> 1, lkh = tid & 1;
    const int aso = swz8(lm, lkh);
    const int blm = lm & 63;
    const bool bpred = tid < 128;
    const int bso = swz8(blm, lkh);

    const unsigned short* Ah = s_ph + (long long)bh_ * Ls * Ls + (long long)(i0 + lm) * Ls + lkh*8;
    const unsigned short* Al = s_pl + (long long)bh_ * Ls * Ls + (long long)(i0 + lm) * Ls + lkh*8;
    const unsigned short* Bh = s_vth + ((long long)b * Dm + h * Hd + blm) * Ls + lkh*8;
    const unsigned short* Bl = s_vtl + ((long long)b * Dm + h * Hd + blm) * Ls + lkh*8;

    const uint32_t aHiS = (uint32_t)__cvta_generic_to_shared(As_hi) + aso*2;
    const uint32_t aLoS = (uint32_t)__cvta_generic_to_shared(As_lo) + aso*2;
    const uint32_t bHiS = (uint32_t)__cvta_generic_to_shared(Bs_hi) + bso*2;
    const uint32_t bLoS = (uint32_t)__cvta_generic_to_shared(Bs_lo) + bso*2;

    const int rA = wm + ((lane >> 3) & 1) * 8 + (lane & 7);
    const uint32_t aOff = (uint32_t)(swz8(rA, (lane >> 4) & 1) * 2);
    const int cB = wn + ((lane >> 4) & 1) * 8 + (lane & 7);
    const uint32_t bOff = (uint32_t)(swz8(cB, (lane >> 3) & 1) * 2);
    const uint32_t aHiB = (uint32_t)__cvta_generic_to_shared(As_hi) + aOff;
    const uint32_t aLoB = (uint32_t)__cvta_generic_to_shared(As_lo) + aOff;
    const uint32_t bHiB = (uint32_t)__cvta_generic_to_shared(Bs_hi) + bOff;
    const uint32_t bLoB = (uint32_t)__cvta_generic_to_shared(Bs_lo) + bOff;

    float acc[2][4][4];
    #pragma unroll
    for (int i = 0; i < 2; i++)
        #pragma unroll
        for (int j = 0; j < 4; j++)
            #pragma unroll
            for (int q = 0; q < 4; q++) acc[i][j][q] = 0.f;

    const int nit = Ls / 16;   // 128
    // non-owning threads (tid>=128) must NOT issue the B copies at all:
    // cp.async with src-size 0 still zero-fills dst, racing the owners' data.
    #define V_ISSUE(s, k0v) {                                               \
        cpa16(aHiS + (uint32_t)(s)*4096, Ah + (k0v), true);                 \
        cpa16(aLoS + (uint32_t)(s)*4096, Al + (k0v), true);                 \
        if (bpred) {                                                        \
            cpa16(bHiS + (uint32_t)(s)*2048, Bh + (k0v), true);             \
            cpa16(bLoS + (uint32_t)(s)*2048, Bl + (k0v), true);             \
        }                                                                   \
        cpa_commit(); }

    #pragma unroll
    for (int s = 0; s < NSG-1; s++) if (s < nit) V_ISSUE(s, s*16);

    int slot = 0, isl = NSG - 1;
    for (int it = 0; it < nit; it++) {
        cpa_wait<NSG-2>();
        __syncthreads();
        const uint32_t stA = (uint32_t)slot * 4096;
        const uint32_t stB = (uint32_t)slot * 2048;
        uint32_t ah[2][4], al[2][4];
        ldsm4(ah[0], aHiB + stA);  ldsm4(ah[1], aHiB + stA + 512);
        ldsm4(al[0], aLoB + stA);  ldsm4(al[1], aLoB + stA + 512);
        #pragma unroll
        for (int p = 0; p < 2; p++) {
            uint32_t bh2[4], bl2[4];
            ldsm4(bh2, bHiB + stB + p * 512);
            ldsm4(bl2, bLoB + stB + p * 512);
            SPLIT_MMA(acc[0][2*p],   acc[1][2*p],   ah, al, (bh2 + 0), (bl2 + 0));
            SPLIT_MMA(acc[0][2*p+1], acc[1][2*p+1], ah, al, (bh2 + 2), (bl2 + 2));
        }
        int nxt = it + NSG - 1;
        if (nxt < nit) { V_ISSUE(isl, nxt*16); } else { cpa_commit(); }
        slot = (slot + 1 == NSG) ? 0 : slot + 1;
        isl  = (isl  + 1 == NSG) ? 0 : isl  + 1;
    }
    #undef V_ISSUE

    #pragma unroll
    for (int mi = 0; mi < 2; mi++) {
        const long long r0 = (long long)b * Ls + i0 + wm + mi * 16 + g;
        #pragma unroll
        for (int nj = 0; nj < 4; nj++) {
            const int c = h * Hd + wn + nj * 8 + tg * 2;
            uint32_t hp, lp;
            bsplit2(acc[mi][nj][0], acc[mi][nj][1], hp, lp);
            *(uint32_t*)&s_ctxh[r0 * Dm + c] = hp;
            *(uint32_t*)&s_ctxl[r0 * Dm + c] = lp;
            bsplit2(acc[mi][nj][2], acc[mi][nj][3], hp, lp);
            *(uint32_t*)&s_ctxh[(r0 + 8) * Dm + c] = hp;
            *(uint32_t*)&s_ctxl[(r0 + 8) * Dm + c] = lp;
        }
    }
}

// ======================== elementwise / small kernels =======================
__global__ void __launch_bounds__(256)
softmax_kernel(float* __restrict__ attn)
{
    const long long row = blockIdx.x;
    float* p = attn + row * (long long)Ls;
    const int tid = threadIdx.x;
    float v[8];
    float mx = -1e30f;
    #pragma unroll
    for (int i = 0; i < 8; i++) { v[i] = p[tid + i*256]; mx = fmaxf(mx, v[i]); }
    mx = blockReduceMax256(mx);
    float s = 0.f;
    #pragma unroll
    for (int i = 0; i < 8; i++) { v[i] = __expf(v[i] - mx); s += v[i]; }
    s = blockReduceSum256(s);
    float inv = 1.f / s;
    #pragma unroll
    for (int i = 0; i < 8; i++) {
        float pv = v[i] * inv;
        long long idx = row * Ls + tid + i*256;
        p[tid + i*256] = pv;
        unsigned short h, l;
        bsplit(pv, h, l);
        s_ph[idx] = h; s_pl[idx] = l;
    }
}

__global__ void __launch_bounds__(256)
add_ln_kernel(const float* __restrict__ a, const float* __restrict__ b,
              const float* __restrict__ gam, const float* __restrict__ bet,
              float* __restrict__ out)
{
    const int t = blockIdx.x, tid = threadIdx.x;
    float v0 = a[(long long)t*Dm + tid]       + b[(long long)t*Dm + tid];
    float v1 = a[(long long)t*Dm + tid + 256] + b[(long long)t*Dm + tid + 256];
    float s = blockReduceSum256(v0 + v1);
    float mean = s * (1.0f / Dm);
    float d0 = v0 - mean, d1 = v1 - mean;
    float sq = blockReduceSum256(d0*d0 + d1*d1);
    float rstd = rsqrtf(sq * (1.0f / Dm) + 1e-5f);
    float o0 = d0 * rstd * gam[tid]       + bet[tid];
    float o1 = d1 * rstd * gam[tid + 256] + bet[tid + 256];
    out[(long long)t*Dm + tid]       = o0;
    out[(long long)t*Dm + tid + 256] = o1;
    unsigned short h, l;
    bsplit(o0, h, l); s_x1h[(long long)t*Dm + tid] = h;       s_x1l[(long long)t*Dm + tid] = l;
    bsplit(o1, h, l); s_x1h[(long long)t*Dm + tid + 256] = h; s_x1l[(long long)t*Dm + tid + 256] = l;
}

__global__ void __launch_bounds__(256)
gate_logits_kernel(const float* __restrict__ gW2, const float* __restrict__ gb2)
{
    const int t = blockIdx.x * 32 + (threadIdx.x >> 3);
    const int e = threadIdx.x & 7;
    const float* row = g_gh + (long long)t * Dm;
    float s = 0.f;
    #pragma unroll 8
    for (int d = 0; d < Dm; d++) s += row[d] * gW2[d*Ee + e];
    g_logits[t*Ee + e] = s + gb2[e];
}

__global__ void init_kernel(float* __restrict__ loss)
{
    if (threadIdx.x < Ee) g_cnt[threadIdx.x] = 0;
    if (threadIdx.x == 0) *loss = 0.0f;
}

__global__ void __launch_bounds__(256)
topk_kernel()
{
    const int t = blockIdx.x * 256 + threadIdx.x;
    if (t >= Tt) return;
    float lg[Ee];
    #pragma unroll
    for (int e = 0; e < Ee; e++) lg[e] = g_logits[t*Ee + e];
    int i1 = 0;
    #pragma unroll
    for (int e = 1; e < Ee; e++) if (lg[e] > lg[i1]) i1 = e;
    int i2 = -1;
    #pragma unroll
    for (int e = 0; e < Ee; e++) if (e != i1 && (i2 < 0 || lg[e] > lg[i2])) i2 = e;
    float mx = lg[i1];
    float s = 0.f;
    #pragma unroll
    for (int e = 0; e < Ee; e++) s += __expf(lg[e] - mx);
    float p1 = __expf(lg[i1] - mx) / s;
    float p2 = __expf(lg[i2] - mx) / s;
    float dn = p1 + p2 + 1e-9f;
    g_wk[2*t + 0] = p1 / dn;
    g_wk[2*t + 1] = p2 / dn;
    int s1 = atomicAdd(&g_cnt[i1], 1); g_list[i1*Tt + s1] = 2*t + 0;
    int s2 = atomicAdd(&g_cnt[i2], 1); g_list[i2*Tt + s2] = 2*t + 1;
}

__global__ void __launch_bounds__(256)
final_ln_kernel(const float* __restrict__ gam, const float* __restrict__ bet,
                float* __restrict__ out)
{
    const int t = blockIdx.x, tid = threadIdx.x;
    const float w0 = g_wk[2*t], w1 = g_wk[2*t + 1];
    float vv[2];
    #pragma unroll
    for (int i = 0; i < 2; i++) {
        int d = tid + i*256;
        float moe = w0 * g_y[(long long)(2*t)   * Dm + d]
                  + w1 * g_y[(long long)(2*t+1) * Dm + d];
        moe = __bfloat162float(__float2bfloat16(moe));
        vv[i] = g_gen[(long long)t*Dm + d] + moe + g_x1[(long long)t*Dm + d];
    }
    float s = blockReduceSum256(vv[0] + vv[1]);
    float mean = s * (1.0f / Dm);
    float d0 = vv[0] - mean, d1 = vv[1] - mean;
    float sq = blockReduceSum256(d0*d0 + d1*d1);
    float rstd = rsqrtf(sq * (1.0f / Dm) + 1e-5f);
    out[(long long)t*Dm + tid]       = d0 * rstd * gam[tid]       + bet[tid];
    out[(long long)t*Dm + tid + 256] = d1 * rstd * gam[tid + 256] + bet[tid + 256];
}

// ------------------------------- launch -------------------------------------
extern "C" void kernel_launch(void* const* d_in, const int* in_sizes, int n_in,
                              void* d_out, int out_size)
{
    const float* x    = (const float*)d_in[0];
    const float* Wq   = (const float*)d_in[1];
    const float* bq   = (const float*)d_in[2];
    const float* Wk   = (const float*)d_in[3];
    const float* bk   = (const float*)d_in[4];
    const float* Wv   = (const float*)d_in[5];
    const float* bv   = (const float*)d_in[6];
    const float* Wo   = (const float*)d_in[7];
    const float* bo   = (const float*)d_in[8];
    const float* ln1g = (const float*)d_in[9];
    const float* ln1b = (const float*)d_in[10];
    const float* gW1  = (const float*)d_in[11];
    const float* gb1  = (const float*)d_in[12];
    const float* gW2  = (const float*)d_in[13];
    const float* gb2  = (const float*)d_in[14];
    const float* eW1  = (const float*)d_in[15];
    const float* eb1  = (const float*)d_in[16];
    const float* eW2  = (const float*)d_in[17];
    const float* eb2  = (const float*)d_in[18];
    const float* geW1 = (const float*)d_in[19];
    const float* geb1 = (const float*)d_in[20];
    const float* geW2 = (const float*)d_in[21];
    const float* geb2 = (const float*)d_in[22];
    const float* ln2g = (const float*)d_in[23];
    const float* ln2b = (const float*)d_in[24];

    float* out  = (float*)d_out;
    float* attn = out + ATTN_OFF;
    float* loss = out + LOSS_OFF;

    float *pv, *ptmp, *px1, *pgh, *pgen;
    cudaGetSymbolAddress((void**)&pv,   g_v);
    cudaGetSymbolAddress((void**)&ptmp, g_tmp);
    cudaGetSymbolAddress((void**)&px1,  g_x1);
    cudaGetSymbolAddress((void**)&pgh,  g_gh);
    cudaGetSymbolAddress((void**)&pgen, g_gen);

    unsigned short *xh,*xl,*qh,*ql,*kh,*kl,*vth,*vtl,*ctxh,*ctxl,*gnh,*gnl;
    unsigned short *wqh,*wql,*wkh,*wkl,*wvh,*wvl,*woh,*wol,*gw1h,*gw1l;
    unsigned short *gew1h,*gew1l,*gew2h,*gew2l,*ew1h,*ew1l,*ew2h,*ew2l;
    cudaGetSymbolAddress((void**)&xh, s_xh);     cudaGetSymbolAddress((void**)&xl, s_xl);
    cudaGetSymbolAddress((void**)&qh, s_qh);     cudaGetSymbolAddress((void**)&ql, s_ql);
    cudaGetSymbolAddress((void**)&kh, s_kh);     cudaGetSymbolAddress((void**)&kl, s_kl);
    cudaGetSymbolAddress((void**)&vth, s_vth);   cudaGetSymbolAddress((void**)&vtl, s_vtl);
    cudaGetSymbolAddress((void**)&ctxh, s_ctxh); cudaGetSymbolAddress((void**)&ctxl, s_ctxl);
    cudaGetSymbolAddress((void**)&gnh, s_gnh);   cudaGetSymbolAddress((void**)&gnl, s_gnl);
    cudaGetSymbolAddress((void**)&wqh, s_wqh);   cudaGetSymbolAddress((void**)&wql, s_wql);
    cudaGetSymbolAddress((void**)&wkh, s_wkh);   cudaGetSymbolAddress((void**)&wkl, s_wkl);
    cudaGetSymbolAddress((void**)&wvh, s_wvh);   cudaGetSymbolAddress((void**)&wvl, s_wvl);
    cudaGetSymbolAddress((void**)&woh, s_woh);   cudaGetSymbolAddress((void**)&wol, s_wol);
    cudaGetSymbolAddress((void**)&gw1h, s_gw1h); cudaGetSymbolAddress((void**)&gw1l, s_gw1l);
    cudaGetSymbolAddress((void**)&gew1h, s_gew1h); cudaGetSymbolAddress((void**)&gew1l, s_gew1l);
    cudaGetSymbolAddress((void**)&gew2h, s_gew2h); cudaGetSymbolAddress((void**)&gew2l, s_gew2l);
    cudaGetSymbolAddress((void**)&ew1h, s_ew1h); cudaGetSymbolAddress((void**)&ew1l, s_ew1l);
    cudaGetSymbolAddress((void**)&ew2h, s_ew2h); cudaGetSymbolAddress((void**)&ew2l, s_ew2l);

    unsigned short *x1h, *x1l;
    cudaGetSymbolAddress((void**)&x1h, s_x1h);   cudaGetSymbolAddress((void**)&x1l, s_x1l);

    const int SMEM_G  = NSG * 2048 * 2 * 4;             // 81920 B (big-K kernels)
    const int SMEM_SC = NS * 2048 * 2 * 4;              // 65536 B (scores)
    const int SMEM_V  = NSG * (2048*2 + 1024*2) * 2;    // 61440 B (attnv)

    // streams/events created on the first (uncaptured) correctness call,
    // reused verbatim during graph capture.
    static cudaStream_t st2 = nullptr, st3 = nullptr;
    static cudaEvent_t evFork, evK, evVT, evW, evX1, evG, evT, evE3;
    static bool init_done = false;
    if (!init_done) {
        cudaFuncSetAttribute(gemm_s<0,0>, cudaFuncAttributeMaxDynamicSharedMemorySize, SMEM_G);
        cudaFuncSetAttribute(gemm_s<0,1>, cudaFuncAttributeMaxDynamicSharedMemorySize, SMEM_G);
        cudaFuncSetAttribute(gemm_s<1,0>, cudaFuncAttributeMaxDynamicSharedMemorySize, SMEM_G);
        cudaFuncSetAttribute(gemm_s<1,1>, cudaFuncAttributeMaxDynamicSharedMemorySize, SMEM_G);
        cudaFuncSetAttribute(expert_s<0>, cudaFuncAttributeMaxDynamicSharedMemorySize, SMEM_G);
        cudaFuncSetAttribute(expert_s<1>, cudaFuncAttributeMaxDynamicSharedMemorySize, SMEM_G);
        cudaFuncSetAttribute(scores_s,    cudaFuncAttributeMaxDynamicSharedMemorySize, SMEM_SC);
        cudaFuncSetAttribute(attnv_s,     cudaFuncAttributeMaxDynamicSharedMemorySize, SMEM_V);
        cudaStreamCreateWithFlags(&st2, cudaStreamNonBlocking);
        cudaStreamCreateWithFlags(&st3, cudaStreamNonBlocking);
        cudaEventCreateWithFlags(&evFork, cudaEventDisableTiming);
        cudaEventCreateWithFlags(&evK,    cudaEventDisableTiming);
        cudaEventCreateWithFlags(&evVT,   cudaEventDisableTiming);
        cudaEventCreateWithFlags(&evW,    cudaEventDisableTiming);
        cudaEventCreateWithFlags(&evX1,   cudaEventDisableTiming);
        cudaEventCreateWithFlags(&evG,    cudaEventDisableTiming);
        cudaEventCreateWithFlags(&evT,    cudaEventDisableTiming);
        cudaEventCreateWithFlags(&evE3,   cudaEventDisableTiming);
        init_done = true;
    }

    dim3 blk(256);
    cudaStream_t s0 = 0;

    // -------- input conversions needed by QKV (on s0) --------
    esplit_kernel<<<(Tt*Dm + 255)/256, blk, 0, s0>>>(x, xh, xl, Tt*Dm);
    wsplit_t_kernel<<<dim3(Dm/32, Dm/32, 1), blk, 0, s0>>>(Wq, wqh, wql, Dm, Dm);
    wsplit_t_kernel<<<dim3(Dm/32, Dm/32, 1), blk, 0, s0>>>(Wk, wkh, wkl, Dm, Dm);
    wsplit_t_kernel<<<dim3(Dm/32, Dm/32, 1), blk, 0, s0>>>(Wv, wvh, wvl, Dm, Dm);
    wsplit_t_kernel<<<dim3(Dm/32, Dm/32, 1), blk, 0, s0>>>(Wo, woh, wol, Dm, Dm);

    // fork: st2 and st3 join after input conversions
    cudaEventRecord(evFork, s0);
    cudaStreamWaitEvent(st2, evFork, 0);
    cudaStreamWaitEvent(st3, evFork, 0);

    // -------- QKV projections, concurrent on 3 streams --------
    gemm_s<0,1><<<dim3(Dm/128, Tt/128), blk, SMEM_G, s0>>>(xh, xl, wqh, wql, bq, nullptr, qh, ql, Dm, Dm);
    gemm_s<0,1><<<dim3(Dm/128, Tt/128), blk, SMEM_G, st2>>>(xh, xl, wkh, wkl, bk, nullptr, kh, kl, Dm, Dm);
    cudaEventRecord(evK, st2);
    gemm_s<0,0><<<dim3(Dm/128, Tt/128), blk, SMEM_G, st3>>>(xh, xl, wvh, wvl, bv, pv, nullptr, nullptr, Dm, Dm);
    // vT transpose on st3 (after V GEMM); concurrent with scores_s on s0.
    wsplit_t_kernel<<<dim3(Dm/32, Ls/32, Bb), blk, 0, st3>>>(pv, vth, vtl, Ls, Dm);
    cudaEventRecord(evVT, st3);

    // st2 (after K): convert gate/gen/expert weight planes, hidden under attention
    wsplit_t_kernel<<<dim3(Dm/32, Dm/32, 1), blk, 0, st2>>>(gW1, gw1h, gw1l, Dm, Dm);
    wsplit_t_kernel<<<dim3(Fd/32, Dm/32, 1), blk, 0, st2>>>(geW1, gew1h, gew1l, Dm, Fd);
    wsplit_t_kernel<<<dim3(Dm/32, Fd/32, 1), blk, 0, st2>>>(geW2, gew2h, gew2l, Fd, Dm);
    wsplit_t_kernel<<<dim3(Fd/32, Dm/32, Ee), blk, 0, st2>>>(eW1, ew1h, ew1l, Dm, Fd);
    wsplit_t_kernel<<<dim3(Dm/32, Fd/32, Ee), blk, 0, st2>>>(eW2, ew2h, ew2l, Fd, Dm);
    cudaEventRecord(evW, st2);

    // -------- attention (s0): scores needs only q (s0) + k (evK) --------
    cudaStreamWaitEvent(s0, evK, 0);
    scores_s<<<dim3(Ls/128, Ls/128, Bb*Hh), blk, SMEM_SC, s0>>>(attn);
    softmax_kernel<<<Bb*Hh*Ls, blk, 0, s0>>>(attn);
    cudaStreamWaitEvent(s0, evVT, 0);
    attnv_s<<<dim3(1, Ls/128, Bb*Hh), blk, SMEM_V, s0>>>();
    gemm_s<0,0><<<dim3(Dm/128, Tt/128), blk, SMEM_G, s0>>>(ctxh, ctxl, woh, wol, bo, ptmp, nullptr, nullptr, Dm, Dm);
    add_ln_kernel<<<Tt, blk, 0, s0>>>(x, ptmp, ln1g, ln1b, px1);
    cudaEventRecord(evX1, s0);

    // -------- general expert on st2, overlapped with routing path ----------
    cudaStreamWaitEvent(st2, evX1, 0);
    gemm_s<1,1><<<dim3(Fd/128, Tt/128), blk, SMEM_G, st2>>>(x1h, x1l, gew1h, gew1l, geb1, nullptr, gnh, gnl, Fd, Dm);
    gemm_s<0,0><<<dim3(Dm/128, Tt/128), blk, SMEM_G, st2>>>(gnh, gnl, gew2h, gew2l, geb2, pgen, nullptr, nullptr, Dm, Fd);
    cudaEventRecord(evG, st2);

    // -------- gate + routing on s0 --------
    cudaStreamWaitEvent(s0, evW, 0);
    gemm_s<1,0><<<dim3(Dm/128, Tt/128), blk, SMEM_G, s0>>>(x1h, x1l, gw1h, gw1l, gb1, pgh, nullptr, nullptr, Dm, Dm);
    gate_logits_kernel<<<Tt/32, blk, 0, s0>>>(gW2, gb2);
    init_kernel<<<1, 32, 0, s0>>>(loss);
    topk_kernel<<<Tt/256, blk, 0, s0>>>();
    cudaEventRecord(evT, s0);

    // -------- routed experts: two batched halves on two streams -----------
    // expert entry sets are disjoint -> cross-half writes are race-free.
    cudaStreamWaitEvent(st3, evT, 0);
    expert_s<0><<<dim3(Fd/128, Tt/128, Ee/2), blk, SMEM_G, s0>>>(ew1h, ew1l, eb1, 0);
    expert_s<1><<<dim3(Dm/128, Tt/128, Ee/2), blk, SMEM_G, s0>>>(ew2h, ew2l, eb2, 0);
    expert_s<0><<<dim3(Fd/128, Tt/128, Ee/2), blk, SMEM_G, st3>>>(ew1h, ew1l, eb1, Ee/2);
    expert_s<1><<<dim3(Dm/128, Tt/128, Ee/2), blk, SMEM_G, st3>>>(ew2h, ew2l, eb2, Ee/2);
    cudaEventRecord(evE3, st3);

    // -------- join + combine + LN2 --------
    cudaStreamWaitEvent(s0, evE3, 0);
    cudaStreamWaitEvent(s0, evG, 0);
    final_ln_kernel<<<Tt, blk, 0, s0>>>(ln2g, ln2b, out);
}

// round 15
// speedup vs baseline: 1.0913x; 1.0913x over previous
#include <cuda_runtime.h>
#include <cuda_bf16.h>
#include <cstdint>

// ---------------------------------------------------------------------------
// MoEEncoderLayer: B=2 L=2048 D=512 H=8 E=8 K=2 DF=2048
// Output layout in d_out (float32): [out: T*D][attn: B*H*L*L][aug_loss: 1]
// bf16x3 split-precision mma.sync m16n8k16; operands pre-split into bf16
// hi/lo planes; GEMM mainloop = cp.async + ldmatrix + mma (k16, NS=4 —
// the proven optimum; NS3/k32 and NS5 variants both regressed).
// Streams: QKV concurrent; vT transpose hidden under scores; general expert
// overlapped with routing; experts in TWO batched halves on two streams.
// ---------------------------------------------------------------------------

#define Bb 2
#define Ls 2048
#define Dm 512
#define Hh 8
#define Ee 8
#define KTOP 2
#define Fd 2048
#define Hd 64
#define Tt (Bb*Ls)                      // 4096
#define NS 4                            // pipeline stages

static const long long ATTN_OFF = (long long)Tt * Dm;                      // 2097152
static const long long LOSS_OFF = ATTN_OFF + (long long)Bb*Hh*Ls*Ls;       // 69206016

// ------------------------- scratch (device globals) ------------------------
__device__ float g_v[Tt*Dm];
__device__ float g_tmp[Tt*Dm];
__device__ float g_x1[Tt*Dm];
__device__ float g_gh[Tt*Dm];
__device__ float g_logits[Tt*Ee];
__device__ float g_wk[Tt*KTOP];
__device__ int   g_cnt[Ee];
__device__ int   g_list[Ee*Tt];
__device__ float g_y[Tt*KTOP*Dm];
__device__ float g_gen[Tt*Dm];

// split planes (bf16 bits as ushort)
__device__ unsigned short s_xh[Tt*Dm],   s_xl[Tt*Dm];
__device__ unsigned short s_qh[Tt*Dm],   s_ql[Tt*Dm];
__device__ unsigned short s_kh[Tt*Dm],   s_kl[Tt*Dm];
__device__ unsigned short s_vth[Tt*Dm],  s_vtl[Tt*Dm];     // vT [Bb][Dm][Ls]
__device__ unsigned short s_ctxh[Tt*Dm], s_ctxl[Tt*Dm];
__device__ unsigned short s_x1h[Tt*Dm],  s_x1l[Tt*Dm];
__device__ unsigned short s_ehh[Tt*KTOP*Fd], s_ehl[Tt*KTOP*Fd];
__device__ unsigned short s_gnh[Tt*Fd],  s_gnl[Tt*Fd];
__device__ unsigned short s_ph[(long long)Bb*Hh*Ls*Ls];
__device__ unsigned short s_pl[(long long)Bb*Hh*Ls*Ls];
// weight planes, transposed to [N x K]
__device__ unsigned short s_wqh[Dm*Dm], s_wql[Dm*Dm];
__device__ unsigned short s_wkh[Dm*Dm], s_wkl[Dm*Dm];
__device__ unsigned short s_wvh[Dm*Dm], s_wvl[Dm*Dm];
__device__ unsigned short s_woh[Dm*Dm], s_wol[Dm*Dm];
__device__ unsigned short s_gw1h[Dm*Dm], s_gw1l[Dm*Dm];
__device__ unsigned short s_gew1h[Fd*Dm], s_gew1l[Fd*Dm];
__device__ unsigned short s_gew2h[Dm*Fd], s_gew2l[Dm*Fd];
__device__ unsigned short s_ew1h[Ee*Fd*Dm], s_ew1l[Ee*Fd*Dm];
__device__ unsigned short s_ew2h[Ee*Dm*Fd], s_ew2l[Ee*Dm*Fd];

// ------------------------------- helpers -----------------------------------
__device__ __forceinline__ float gelu_tanh(float x) {
    float x3 = x * x * x;
    float t  = tanhf(0.7978845608028654f * (x + 0.044715f * x3));
    return 0.5f * x * (1.0f + t);
}
__device__ __forceinline__ void bsplit(float x, unsigned short& h, unsigned short& l) {
    __nv_bfloat16 hb = __float2bfloat16_rn(x);
    float hf = __bfloat162float(hb);
    __nv_bfloat16 lb = __float2bfloat16_rn(x - hf);
    h = __bfloat16_as_ushort(hb);
    l = __bfloat16_as_ushort(lb);
}
__device__ __forceinline__ void bsplit2(float x0, float x1, uint32_t& hp, uint32_t& lp) {
    unsigned short h0, l0, h1, l1;
    bsplit(x0, h0, l0);
    bsplit(x1, h1, l1);
    hp = (uint32_t)h0 | ((uint32_t)h1 << 16);
    lp = (uint32_t)l0 | ((uint32_t)l1 << 16);
}
__device__ __forceinline__ void mma16(float* c, const uint32_t* a, const uint32_t* b) {
    asm volatile(
        "mma.sync.aligned.m16n8k16.row.col.f32.bf16.bf16.f32 "
        "{%0,%1,%2,%3}, {%4,%5,%6,%7}, {%8,%9}, {%0,%1,%2,%3};"
        : "+f"(c[0]), "+f"(c[1]), "+f"(c[2]), "+f"(c[3])
        : "r"(a[0]), "r"(a[1]), "r"(a[2]), "r"(a[3]), "r"(b[0]), "r"(b[1]));
}
__device__ __forceinline__ void ldsm4(uint32_t* d, uint32_t addr) {
    asm volatile("ldmatrix.sync.aligned.m8n8.x4.shared.b16 {%0,%1,%2,%3}, [%4];"
        : "=r"(d[0]), "=r"(d[1]), "=r"(d[2]), "=r"(d[3]) : "r"(addr));
}
__device__ __forceinline__ void cpa16(uint32_t dst, const void* src, bool pred) {
    int sz = pred ? 16 : 0;
    asm volatile("cp.async.cg.shared.global [%0], [%1], 16, %2;\n"
        :: "r"(dst), "l"(src), "r"(sz));
}
__device__ __forceinline__ void cpa_commit() { asm volatile("cp.async.commit_group;"); }
template<int N> __device__ __forceinline__ void cpa_wait() {
    asm volatile("cp.async.wait_group %0;" :: "n"(N));
}
__device__ __forceinline__ int swz8(int row, int khalf) {
    return row * 16 + ((khalf ^ ((row >> 2) & 1)) << 3);
}

__device__ __forceinline__ float warpReduceSum(float v) {
    #pragma unroll
    for (int o = 16; o > 0; o >>= 1) v += __shfl_xor_sync(0xffffffffu, v, o);
    return v;
}
__device__ __forceinline__ float warpReduceMax(float v) {
    #pragma unroll
    for (int o = 16; o > 0; o >>= 1) v = fmaxf(v, __shfl_xor_sync(0xffffffffu, v, o));
    return v;
}
__device__ __forceinline__ float blockReduceSum256(float v) {
    __shared__ float sh[33];
    int tid = threadIdx.x, lane = tid & 31, wid = tid >> 5;
    v = warpReduceSum(v);
    if (lane == 0) sh[wid] = v;
    __syncthreads();
    if (tid < 8) {
        float x = sh[tid];
        #pragma unroll
        for (int o = 4; o > 0; o >>= 1) x += __shfl_xor_sync(0xffu, x, o);
        if (tid == 0) sh[32] = x;
    }
    __syncthreads();
    float r = sh[32];
    __syncthreads();
    return r;
}
__device__ __forceinline__ float blockReduceMax256(float v) {
    __shared__ float sh[33];
    int tid = threadIdx.x, lane = tid & 31, wid = tid >> 5;
    v = warpReduceMax(v);
    if (lane == 0) sh[wid] = v;
    __syncthreads();
    if (tid < 8) {
        float x = sh[tid];
        #pragma unroll
        for (int o = 4; o > 0; o >>= 1) x = fmaxf(x, __shfl_xor_sync(0xffu, x, o));
        if (tid == 0) sh[32] = x;
    }
    __syncthreads();
    float r = sh[32];
    __syncthreads();
    return r;
}

#define SPLIT_MMA(ACC0, ACC1, AH, AL, BH, BL)                             \
    mma16(ACC0, AH[0], BH); mma16(ACC1, AH[1], BH);                        \
    mma16(ACC0, AL[0], BH); mma16(ACC1, AL[1], BH);                        \
    mma16(ACC0, AH[0], BL); mma16(ACC1, AH[1], BL);

// ======================= conversion kernels ================================
__global__ void __launch_bounds__(256)
esplit_kernel(const float* __restrict__ in, unsigned short* __restrict__ oh,
              unsigned short* __restrict__ ol, int n)
{
    int i = blockIdx.x * 256 + threadIdx.x;
    if (i < n) {
        unsigned short h, l;
        bsplit(in[i], h, l);
        oh[i] = h; ol[i] = l;
    }
}

// in [K x N] fp32 (batched) -> planes [N x K] bf16 hi/lo (batched)
__global__ void __launch_bounds__(256)
wsplit_t_kernel(const float* __restrict__ in, unsigned short* __restrict__ oh,
                unsigned short* __restrict__ ol, int K, int N)
{
    __shared__ float t[32][33];
    long long base = (long long)blockIdx.z * K * N;
    int n0 = blockIdx.x * 32, k0 = blockIdx.y * 32;
    int tx = threadIdx.x & 31, ty = threadIdx.x >> 5;   // (32, 8)
    #pragma unroll
    for (int i = 0; i < 4; i++)
        t[ty + i*8][tx] = in[base + (long long)(k0 + ty + i*8) * N + n0 + tx];
    __syncthreads();
    #pragma unroll
    for (int i = 0; i < 4; i++) {
        unsigned short h, l;
        bsplit(t[tx][ty + i*8], h, l);
        long long o = base + (long long)(n0 + ty + i*8) * K + k0 + tx;
        oh[o] = h; ol[o] = l;
    }
}

// ===================== generic GEMM (pre-split planes) ======================
// C = act(A @ W + bias); A planes [M x Kd]; B planes [N x Kd] (pre-transposed)
// OMODE: 0 = fp32 C, 1 = split planes C
template<int ACT, int OMODE>
__global__ void __launch_bounds__(256)
gemm_s(const unsigned short* __restrict__ Ahi, const unsigned short* __restrict__ Alo,
       const unsigned short* __restrict__ Bhi, const unsigned short* __restrict__ Blo,
       const float* __restrict__ bias, float* __restrict__ Cf,
       unsigned short* __restrict__ Chi, unsigned short* __restrict__ Clo,
       int N, int Kd)
{
    extern __shared__ unsigned short sm[];
    unsigned short* As_hi = sm;
    unsigned short* As_lo = sm + NS*2048;
    unsigned short* Bs_hi = sm + 2*NS*2048;
    unsigned short* Bs_lo = sm + 3*NS*2048;

    const int tid = threadIdx.x, lane = tid & 31, wid = tid >> 5;
    const int g = lane >> 2, tg = lane & 3;
    const int wm = (wid & 3) * 32, wn = (wid >> 2) * 64;
    const int m0 = blockIdx.y * 128, n0 = blockIdx.x * 128;

    const int lm = tid >> 1, lkh = tid & 1;
    const int aso = swz8(lm, lkh);

    const unsigned short* Ah = Ahi + (long long)(m0 + lm) * Kd + lkh * 8;
    const unsigned short* Al = Alo + (long long)(m0 + lm) * Kd + lkh * 8;
    const unsigned short* Bh = Bhi + (long long)(n0 + lm) * Kd + lkh * 8;
    const unsigned short* Bl = Blo + (long long)(n0 + lm) * Kd + lkh * 8;

    const uint32_t aHiS = (uint32_t)__cvta_generic_to_shared(As_hi) + aso*2;
    const uint32_t aLoS = (uint32_t)__cvta_generic_to_shared(As_lo) + aso*2;
    const uint32_t bHiS = (uint32_t)__cvta_generic_to_shared(Bs_hi) + aso*2;
    const uint32_t bLoS = (uint32_t)__cvta_generic_to_shared(Bs_lo) + aso*2;

    const int rA = wm + ((lane >> 3) & 1) * 8 + (lane & 7);
    const uint32_t aOff = (uint32_t)(swz8(rA, (lane >> 4) & 1) * 2);
    const int cB = wn + ((lane >> 4) & 1) * 8 + (lane & 7);
    const uint32_t bOff = (uint32_t)(swz8(cB, (lane >> 3) & 1) * 2);
    const uint32_t aHiB = (uint32_t)__cvta_generic_to_shared(As_hi) + aOff;
    const uint32_t aLoB = (uint32_t)__cvta_generic_to_shared(As_lo) + aOff;
    const uint32_t bHiB = (uint32_t)__cvta_generic_to_shared(Bs_hi) + bOff;
    const uint32_t bLoB = (uint32_t)__cvta_generic_to_shared(Bs_lo) + bOff;

    float acc[2][8][4];
    #pragma unroll
    for (int i = 0; i < 2; i++)
        #pragma unroll
        for (int j = 0; j < 8; j++)
            #pragma unroll
            for (int q = 0; q < 4; q++) acc[i][j][q] = 0.f;

    const int nit = Kd / 16;
    #define G_ISSUE(s, k0v) { uint32_t o = (uint32_t)(s)*4096;              \
        cpa16(aHiS + o, Ah + (k0v), true); cpa16(aLoS + o, Al + (k0v), true);\
        cpa16(bHiS + o, Bh + (k0v), true); cpa16(bLoS + o, Bl + (k0v), true);\
        cpa_commit(); }

    #pragma unroll
    for (int s = 0; s < NS-1; s++) if (s < nit) G_ISSUE(s, s*16);

    for (int it = 0; it < nit; it++) {
        cpa_wait<NS-2>();
        __syncthreads();
        const uint32_t st = (uint32_t)(it & (NS-1)) * 4096;
        uint32_t ah[2][4], al[2][4];
        ldsm4(ah[0], aHiB + st);  ldsm4(ah[1], aHiB + st + 512);
        ldsm4(al[0], aLoB + st);  ldsm4(al[1], aLoB + st + 512);
        #pragma unroll
        for (int p = 0; p < 4; p++) {
            uint32_t bh[4], bl[4];
            ldsm4(bh, bHiB + st + p * 512);
            ldsm4(bl, bLoB + st + p * 512);
            SPLIT_MMA(acc[0][2*p],   acc[1][2*p],   ah, al, (bh + 0), (bl + 0));
            SPLIT_MMA(acc[0][2*p+1], acc[1][2*p+1], ah, al, (bh + 2), (bl + 2));
        }
        int nxt = it + NS - 1;
        if (nxt < nit) { G_ISSUE(nxt & (NS-1), nxt*16); } else { cpa_commit(); }
    }
    #undef G_ISSUE

    #pragma unroll
    for (int mi = 0; mi < 2; mi++) {
        const int r0 = m0 + wm + mi * 16 + g;
        #pragma unroll
        for (int nj = 0; nj < 8; nj++) {
            const int c = n0 + wn + nj * 8 + tg * 2;
            const float b0v = bias[c], b1v = bias[c + 1];
            float v0 = acc[mi][nj][0] + b0v, v1 = acc[mi][nj][1] + b1v;
            float v2 = acc[mi][nj][2] + b0v, v3 = acc[mi][nj][3] + b1v;
            if (ACT) { v0 = gelu_tanh(v0); v1 = gelu_tanh(v1); v2 = gelu_tanh(v2); v3 = gelu_tanh(v3); }
            if (OMODE == 0) {
                *(float2*)&Cf[(long long)r0 * N + c]       = make_float2(v0, v1);
                *(float2*)&Cf[(long long)(r0 + 8) * N + c] = make_float2(v2, v3);
            } else {
                uint32_t hp, lp;
                bsplit2(v0, v1, hp, lp);
                *(uint32_t*)&Chi[(long long)r0 * N + c] = hp;
                *(uint32_t*)&Clo[(long long)r0 * N + c] = lp;
                bsplit2(v2, v3, hp, lp);
                *(uint32_t*)&Chi[(long long)(r0 + 8) * N + c] = hp;
                *(uint32_t*)&Clo[(long long)(r0 + 8) * N + c] = lp;
            }
        }
    }
}

// ==================  gathered expert GEMMs (batched, e-offset) ==============
// MODE 0: eh[ent] = gelu(x1[ent>>1] @ eW1[e] + eb1[e])   (N=Fd, Kd=Dm)
// MODE 1: y[ent]  = eh[ent] @ eW2[e] + eb2[e]            (N=Dm, Kd=Fd)
// e = e0 + blockIdx.z (half-split: two launches of z-dim Ee/2)
template<int MODE>
__global__ void __launch_bounds__(256)
expert_s(const unsigned short* __restrict__ Whi, const unsigned short* __restrict__ Wlo,
         const float* __restrict__ bias, const int e0)
{
    const int e = e0 + blockIdx.z;
    const int cnt = g_cnt[e];
    const int r0blk = blockIdx.y * 128;
    if (r0blk >= cnt) return;

    const int N  = MODE ? Dm : Fd;
    const int Kd = MODE ? Fd : Dm;

    extern __shared__ unsigned short sm[];
    unsigned short* As_hi = sm;
    unsigned short* As_lo = sm + NS*2048;
    unsigned short* Bs_hi = sm + 2*NS*2048;
    unsigned short* Bs_lo = sm + 3*NS*2048;
    __shared__ int toks[128];

    const int tid = threadIdx.x, lane = tid & 31, wid = tid >> 5;
    const int g = lane >> 2, tg = lane & 3;
    const int wm = (wid & 3) * 32, wn = (wid >> 2) * 64;
    const int n0 = blockIdx.x * 128;

    if (tid < 128) {
        int r = r0blk + tid;
        toks[tid] = (r < cnt) ? g_list[e * Tt + r] : -1;
    }
    __syncthreads();

    const int lm = tid >> 1, lkh = tid & 1;
    const int aso = swz8(lm, lkh);

    const int entA = toks[lm];
    const bool apred = (entA >= 0);
    long long arow = apred ? (MODE ? (long long)entA : (long long)(entA >> 1)) : 0;
    const unsigned short* Ahp = (MODE ? s_ehh : s_x1h) + arow * Kd + lkh * 8;
    const unsigned short* Alp = (MODE ? s_ehl : s_x1l) + arow * Kd + lkh * 8;
    const unsigned short* Bhp = Whi + (long long)e * Dm * Fd + (long long)(n0 + lm) * Kd + lkh * 8;
    const unsigned short* Blp = Wlo + (long long)e * Dm * Fd + (long long)(n0 + lm) * Kd + lkh * 8;
    const float* bp = bias + (long long)e * N;

    const uint32_t aHiS = (uint32_t)__cvta_generic_to_shared(As_hi) + aso*2;
    const uint32_t aLoS = (uint32_t)__cvta_generic_to_shared(As_lo) + aso*2;
    const uint32_t bHiS = (uint32_t)__cvta_generic_to_shared(Bs_hi) + aso*2;
    const uint32_t bLoS = (uint32_t)__cvta_generic_to_shared(Bs_lo) + aso*2;

    const int rA = wm + ((lane >> 3) & 1) * 8 + (lane & 7);
    const uint32_t aOff = (uint32_t)(swz8(rA, (lane >> 4) & 1) * 2);
    const int cB = wn + ((lane >> 4) & 1) * 8 + (lane & 7);
    const uint32_t bOff = (uint32_t)(swz8(cB, (lane >> 3) & 1) * 2);
    const uint32_t aHiB = (uint32_t)__cvta_generic_to_shared(As_hi) + aOff;
    const uint32_t aLoB = (uint32_t)__cvta_generic_to_shared(As_lo) + aOff;
    const uint32_t bHiB = (uint32_t)__cvta_generic_to_shared(Bs_hi) + bOff;
    const uint32_t bLoB = (uint32_t)__cvta_generic_to_shared(Bs_lo) + bOff;

    float acc[2][8][4];
    #pragma unroll
    for (int i = 0; i < 2; i++)
        #pragma unroll
        for (int j = 0; j < 8; j++)
            #pragma unroll
            for (int q = 0; q < 4; q++) acc[i][j][q] = 0.f;

    const int nit = Kd / 16;
    #define E_ISSUE(s, k0v) { uint32_t o = (uint32_t)(s)*4096;                 \
        cpa16(aHiS + o, Ahp + (k0v), apred); cpa16(aLoS + o, Alp + (k0v), apred);\
        cpa16(bHiS + o, Bhp + (k0v), true);  cpa16(bLoS + o, Blp + (k0v), true); \
        cpa_commit(); }

    #pragma unroll
    for (int s = 0; s < NS-1; s++) if (s < nit) E_ISSUE(s, s*16);

    for (int it = 0; it < nit; it++) {
        cpa_wait<NS-2>();
        __syncthreads();
        const uint32_t st = (uint32_t)(it & (NS-1)) * 4096;
        uint32_t ah[2][4], al[2][4];
        ldsm4(ah[0], aHiB + st);  ldsm4(ah[1], aHiB + st + 512);
        ldsm4(al[0], aLoB + st);  ldsm4(al[1], aLoB + st + 512);
        #pragma unroll
        for (int p = 0; p < 4; p++) {
            uint32_t bh[4], bl[4];
            ldsm4(bh, bHiB + st + p * 512);
            ldsm4(bl, bLoB + st + p * 512);
            SPLIT_MMA(acc[0][2*p],   acc[1][2*p],   ah, al, (bh + 0), (bl + 0));
            SPLIT_MMA(acc[0][2*p+1], acc[1][2*p+1], ah, al, (bh + 2), (bl + 2));
        }
        int nxt = it + NS - 1;
        if (nxt < nit) { E_ISSUE(nxt & (NS-1), nxt*16); } else { cpa_commit(); }
    }
    #undef E_ISSUE

    #pragma unroll
    for (int mi = 0; mi < 2; mi++) {
        const int rr0 = wm + mi * 16 + g;
        const int ent0 = toks[rr0], ent1 = toks[rr0 + 8];
        #pragma unroll
        for (int nj = 0; nj < 8; nj++) {
            const int c = wn + nj * 8 + tg * 2;
            const float b0v = bp[n0 + c], b1v = bp[n0 + c + 1];
            if (ent0 >= 0) {
                float v0 = acc[mi][nj][0] + b0v, v1 = acc[mi][nj][1] + b1v;
                if (MODE == 0) {
                    v0 = gelu_tanh(v0); v1 = gelu_tanh(v1);
                    uint32_t hp, lp;
                    bsplit2(v0, v1, hp, lp);
                    *(uint32_t*)&s_ehh[(long long)ent0 * Fd + n0 + c] = hp;
                    *(uint32_t*)&s_ehl[(long long)ent0 * Fd + n0 + c] = lp;
                } else {
                    *(float2*)&g_y[(long long)ent0 * Dm + n0 + c] = make_float2(v0, v1);
                }
            }
            if (ent1 >= 0) {
                float v2 = acc[mi][nj][2] + b0v, v3 = acc[mi][nj][3] + b1v;
                if (MODE == 0) {
                    v2 = gelu_tanh(v2); v3 = gelu_tanh(v3);
                    uint32_t hp, lp;
                    bsplit2(v2, v3, hp, lp);
                    *(uint32_t*)&s_ehh[(long long)ent1 * Fd + n0 + c] = hp;
                    *(uint32_t*)&s_ehl[(long long)ent1 * Fd + n0 + c] = lp;
                } else {
                    *(float2*)&g_y[(long long)ent1 * Dm + n0 + c] = make_float2(v2, v3);
                }
            }
        }
    }
}

// ================  attention scores: Q K^T / 8  =============================
__global__ void __launch_bounds__(256)
scores_s(float* __restrict__ attn)
{
    extern __shared__ unsigned short sm[];
    unsigned short* As_hi = sm;
    unsigned short* As_lo = sm + NS*2048;
    unsigned short* Bs_hi = sm + 2*NS*2048;
    unsigned short* Bs_lo = sm + 3*NS*2048;

    const int tid = threadIdx.x, lane = tid & 31, wid = tid >> 5;
    const int g = lane >> 2, tg = lane & 3;
    const int wm = (wid & 3) * 32, wn = (wid >> 2) * 64;
    const int bh_ = blockIdx.z; const int b = bh_ >> 3, h = bh_ & 7;
    const int i0 = blockIdx.y * 128, j0 = blockIdx.x * 128;

    const int lm = tid >> 1, lkh = tid & 1;
    const int aso = swz8(lm, lkh);

    const unsigned short* Ah = s_qh + (long long)(b*Ls + i0 + lm) * Dm + h*Hd + lkh*8;
    const unsigned short* Al = s_ql + (long long)(b*Ls + i0 + lm) * Dm + h*Hd + lkh*8;
    const unsigned short* Bh = s_kh + (long long)(b*Ls + j0 + lm) * Dm + h*Hd + lkh*8;
    const unsigned short* Bl = s_kl + (long long)(b*Ls + j0 + lm) * Dm + h*Hd + lkh*8;

    const uint32_t aHiS = (uint32_t)__cvta_generic_to_shared(As_hi) + aso*2;
    const uint32_t aLoS = (uint32_t)__cvta_generic_to_shared(As_lo) + aso*2;
    const uint32_t bHiS = (uint32_t)__cvta_generic_to_shared(Bs_hi) + aso*2;
    const uint32_t bLoS = (uint32_t)__cvta_generic_to_shared(Bs_lo) + aso*2;

    const int rA = wm + ((lane >> 3) & 1) * 8 + (lane & 7);
    const uint32_t aOff = (uint32_t)(swz8(rA, (lane >> 4) & 1) * 2);
    const int cB = wn + ((lane >> 4) & 1) * 8 + (lane & 7);
    const uint32_t bOff = (uint32_t)(swz8(cB, (lane >> 3) & 1) * 2);
    const uint32_t aHiB = (uint32_t)__cvta_generic_to_shared(As_hi) + aOff;
    const uint32_t aLoB = (uint32_t)__cvta_generic_to_shared(As_lo) + aOff;
    const uint32_t bHiB = (uint32_t)__cvta_generic_to_shared(Bs_hi) + bOff;
    const uint32_t bLoB = (uint32_t)__cvta_generic_to_shared(Bs_lo) + bOff;

    float acc[2][8][4];
    #pragma unroll
    for (int i = 0; i < 2; i++)
        #pragma unroll
        for (int j = 0; j < 8; j++)
            #pragma unroll
            for (int q2 = 0; q2 < 4; q2++) acc[i][j][q2] = 0.f;

    const int nit = Hd / 16;   // 4
    #define S_ISSUE(s, k0v) { uint32_t o = (uint32_t)(s)*4096;              \
        cpa16(aHiS + o, Ah + (k0v), true); cpa16(aLoS + o, Al + (k0v), true);\
        cpa16(bHiS + o, Bh + (k0v), true); cpa16(bLoS + o, Bl + (k0v), true);\
        cpa_commit(); }

    #pragma unroll
    for (int s = 0; s < NS-1; s++) if (s < nit) S_ISSUE(s, s*16);

    for (int it = 0; it < nit; it++) {
        cpa_wait<NS-2>();
        __syncthreads();
        const uint32_t st = (uint32_t)(it & (NS-1)) * 4096;
        uint32_t ah[2][4], al[2][4];
        ldsm4(ah[0], aHiB + st);  ldsm4(ah[1], aHiB + st + 512);
        ldsm4(al[0], aLoB + st);  ldsm4(al[1], aLoB + st + 512);
        #pragma unroll
        for (int p = 0; p < 4; p++) {
            uint32_t bh2[4], bl2[4];
            ldsm4(bh2, bHiB + st + p * 512);
            ldsm4(bl2, bLoB + st + p * 512);
            SPLIT_MMA(acc[0][2*p],   acc[1][2*p],   ah, al, (bh2 + 0), (bl2 + 0));
            SPLIT_MMA(acc[0][2*p+1], acc[1][2*p+1], ah, al, (bh2 + 2), (bl2 + 2));
        }
        int nxt = it + NS - 1;
        if (nxt < nit) { S_ISSUE(nxt & (NS-1), nxt*16); } else { cpa_commit(); }
    }
    #undef S_ISSUE

    float* O = attn + (long long)bh_ * Ls * Ls;
    #pragma unroll
    for (int mi = 0; mi < 2; mi++) {
        const int r0 = i0 + wm + mi * 16 + g;
        #pragma unroll
        for (int nj = 0; nj < 8; nj++) {
            const int c = j0 + wn + nj * 8 + tg * 2;
            *(float2*)&O[(long long)r0 * Ls + c] =
                make_float2(acc[mi][nj][0] * 0.125f, acc[mi][nj][1] * 0.125f);
            *(float2*)&O[(long long)(r0 + 8) * Ls + c] =
                make_float2(acc[mi][nj][2] * 0.125f, acc[mi][nj][3] * 0.125f);
        }
    }
}

// =====================  P @ V  ==============================================
// grid = (1, L/128, B*H).  Block 128x64, warp 32x32, Kd = L = 2048.
__global__ void __launch_bounds__(256)
attnv_s()
{
    extern __shared__ unsigned short sm[];
    unsigned short* As_hi = sm;                 // NS*2048
    unsigned short* As_lo = sm + NS*2048;
    unsigned short* Bs_hi = sm + 2*NS*2048;     // NS*1024
    unsigned short* Bs_lo = sm + 2*NS*2048 + NS*1024;

    const int tid = threadIdx.x, lane = tid & 31, wid = tid >> 5;
    const int g = lane >> 2, tg = lane & 3;
    const int wm = (wid & 3) * 32, wn = (wid >> 2) * 32;
    const int bh_ = blockIdx.z; const int b = bh_ >> 3, h = bh_ & 7;
    const int i0 = blockIdx.y * 128;

    const int lm = tid >> 1, lkh = tid & 1;
    const int aso = swz8(lm, lkh);
    const int blm = lm & 63;
    const bool bpred = tid < 128;
    const int bso = swz8(blm, lkh);

    const unsigned short* Ah = s_ph + (long long)bh_ * Ls * Ls + (long long)(i0 + lm) * Ls + lkh*8;
    const unsigned short* Al = s_pl + (long long)bh_ * Ls * Ls + (long long)(i0 + lm) * Ls + lkh*8;
    const unsigned short* Bh = s_vth + ((long long)b * Dm + h * Hd + blm) * Ls + lkh*8;
    const unsigned short* Bl = s_vtl + ((long long)b * Dm + h * Hd + blm) * Ls + lkh*8;

    const uint32_t aHiS = (uint32_t)__cvta_generic_to_shared(As_hi) + aso*2;
    const uint32_t aLoS = (uint32_t)__cvta_generic_to_shared(As_lo) + aso*2;
    const uint32_t bHiS = (uint32_t)__cvta_generic_to_shared(Bs_hi) + bso*2;
    const uint32_t bLoS = (uint32_t)__cvta_generic_to_shared(Bs_lo) + bso*2;

    const int rA = wm + ((lane >> 3) & 1) * 8 + (lane & 7);
    const uint32_t aOff = (uint32_t)(swz8(rA, (lane >> 4) & 1) * 2);
    const int cB = wn + ((lane >> 4) & 1) * 8 + (lane & 7);
    const uint32_t bOff = (uint32_t)(swz8(cB, (lane >> 3) & 1) * 2);
    const uint32_t aHiB = (uint32_t)__cvta_generic_to_shared(As_hi) + aOff;
    const uint32_t aLoB = (uint32_t)__cvta_generic_to_shared(As_lo) + aOff;
    const uint32_t bHiB = (uint32_t)__cvta_generic_to_shared(Bs_hi) + bOff;
    const uint32_t bLoB = (uint32_t)__cvta_generic_to_shared(Bs_lo) + bOff;

    float acc[2][4][4];
    #pragma unroll
    for (int i = 0; i < 2; i++)
        #pragma unroll
        for (int j = 0; j < 4; j++)
            #pragma unroll
            for (int q = 0; q < 4; q++) acc[i][j][q] = 0.f;

    const int nit = Ls / 16;   // 128
    // non-owning threads (tid>=128) must NOT issue the B copies at all:
    // cp.async with src-size 0 still zero-fills dst, racing the owners' data.
    #define V_ISSUE(s, k0v) {                                               \
        cpa16(aHiS + (uint32_t)(s)*4096, Ah + (k0v), true);                 \
        cpa16(aLoS + (uint32_t)(s)*4096, Al + (k0v), true);                 \
        if (bpred) {                                                        \
            cpa16(bHiS + (uint32_t)(s)*2048, Bh + (k0v), true);             \
            cpa16(bLoS + (uint32_t)(s)*2048, Bl + (k0v), true);             \
        }                                                                   \
        cpa_commit(); }

    #pragma unroll
    for (int s = 0; s < NS-1; s++) if (s < nit) V_ISSUE(s, s*16);

    for (int it = 0; it < nit; it++) {
        cpa_wait<NS-2>();
        __syncthreads();
        const uint32_t stA = (uint32_t)(it & (NS-1)) * 4096;
        const uint32_t stB = (uint32_t)(it & (NS-1)) * 2048;
        uint32_t ah[2][4], al[2][4];
        ldsm4(ah[0], aHiB + stA);  ldsm4(ah[1], aHiB + stA + 512);
        ldsm4(al[0], aLoB + stA);  ldsm4(al[1], aLoB + stA + 512);
        #pragma unroll
        for (int p = 0; p < 2; p++) {
            uint32_t bh2[4], bl2[4];
            ldsm4(bh2, bHiB + stB + p * 512);
            ldsm4(bl2, bLoB + stB + p * 512);
            SPLIT_MMA(acc[0][2*p],   acc[1][2*p],   ah, al, (bh2 + 0), (bl2 + 0));
            SPLIT_MMA(acc[0][2*p+1], acc[1][2*p+1], ah, al, (bh2 + 2), (bl2 + 2));
        }
        int nxt = it + NS - 1;
        if (nxt < nit) { V_ISSUE(nxt & (NS-1), nxt*16); } else { cpa_commit(); }
    }
    #undef V_ISSUE

    #pragma unroll
    for (int mi = 0; mi < 2; mi++) {
        const long long r0 = (long long)b * Ls + i0 + wm + mi * 16 + g;
        #pragma unroll
        for (int nj = 0; nj < 4; nj++) {
            const int c = h * Hd + wn + nj * 8 + tg * 2;
            uint32_t hp, lp;
            bsplit2(acc[mi][nj][0], acc[mi][nj][1], hp, lp);
            *(uint32_t*)&s_ctxh[r0 * Dm + c] = hp;
            *(uint32_t*)&s_ctxl[r0 * Dm + c] = lp;
            bsplit2(acc[mi][nj][2], acc[mi][nj][3], hp, lp);
            *(uint32_t*)&s_ctxh[(r0 + 8) * Dm + c] = hp;
            *(uint32_t*)&s_ctxl[(r0 + 8) * Dm + c] = lp;
        }
    }
}

// ======================== elementwise / small kernels =======================
__global__ void __launch_bounds__(256)
softmax_kernel(float* __restrict__ attn)
{
    const long long row = blockIdx.x;
    float* p = attn + row * (long long)Ls;
    const int tid = threadIdx.x;
    float v[8];
    float mx = -1e30f;
    #pragma unroll
    for (int i = 0; i < 8; i++) { v[i] = p[tid + i*256]; mx = fmaxf(mx, v[i]); }
    mx = blockReduceMax256(mx);
    float s = 0.f;
    #pragma unroll
    for (int i = 0; i < 8; i++) { v[i] = __expf(v[i] - mx); s += v[i]; }
    s = blockReduceSum256(s);
    float inv = 1.f / s;
    #pragma unroll
    for (int i = 0; i < 8; i++) {
        float pv = v[i] * inv;
        long long idx = row * Ls + tid + i*256;
        p[tid + i*256] = pv;
        unsigned short h, l;
        bsplit(pv, h, l);
        s_ph[idx] = h; s_pl[idx] = l;
    }
}

__global__ void __launch_bounds__(256)
add_ln_kernel(const float* __restrict__ a, const float* __restrict__ b,
              const float* __restrict__ gam, const float* __restrict__ bet,
              float* __restrict__ out)
{
    const int t = blockIdx.x, tid = threadIdx.x;
    float v0 = a[(long long)t*Dm + tid]       + b[(long long)t*Dm + tid];
    float v1 = a[(long long)t*Dm + tid + 256] + b[(long long)t*Dm + tid + 256];
    float s = blockReduceSum256(v0 + v1);
    float mean = s * (1.0f / Dm);
    float d0 = v0 - mean, d1 = v1 - mean;
    float sq = blockReduceSum256(d0*d0 + d1*d1);
    float rstd = rsqrtf(sq * (1.0f / Dm) + 1e-5f);
    float o0 = d0 * rstd * gam[tid]       + bet[tid];
    float o1 = d1 * rstd * gam[tid + 256] + bet[tid + 256];
    out[(long long)t*Dm + tid]       = o0;
    out[(long long)t*Dm + tid + 256] = o1;
    unsigned short h, l;
    bsplit(o0, h, l); s_x1h[(long long)t*Dm + tid] = h;       s_x1l[(long long)t*Dm + tid] = l;
    bsplit(o1, h, l); s_x1h[(long long)t*Dm + tid + 256] = h; s_x1l[(long long)t*Dm + tid + 256] = l;
}

__global__ void __launch_bounds__(256)
gate_logits_kernel(const float* __restrict__ gW2, const float* __restrict__ gb2)
{
    const int t = blockIdx.x * 32 + (threadIdx.x >> 3);
    const int e = threadIdx.x & 7;
    const float* row = g_gh + (long long)t * Dm;
    float s = 0.f;
    #pragma unroll 8
    for (int d = 0; d < Dm; d++) s += row[d] * gW2[d*Ee + e];
    g_logits[t*Ee + e] = s + gb2[e];
}

__global__ void init_kernel(float* __restrict__ loss)
{
    if (threadIdx.x < Ee) g_cnt[threadIdx.x] = 0;
    if (threadIdx.x == 0) *loss = 0.0f;
}

__global__ void __launch_bounds__(256)
topk_kernel()
{
    const int t = blockIdx.x * 256 + threadIdx.x;
    if (t >= Tt) return;
    float lg[Ee];
    #pragma unroll
    for (int e = 0; e < Ee; e++) lg[e] = g_logits[t*Ee + e];
    int i1 = 0;
    #pragma unroll
    for (int e = 1; e < Ee; e++) if (lg[e] > lg[i1]) i1 = e;
    int i2 = -1;
    #pragma unroll
    for (int e = 0; e < Ee; e++) if (e != i1 && (i2 < 0 || lg[e] > lg[i2])) i2 = e;
    float mx = lg[i1];
    float s = 0.f;
    #pragma unroll
    for (int e = 0; e < Ee; e++) s += __expf(lg[e] - mx);
    float p1 = __expf(lg[i1] - mx) / s;
    float p2 = __expf(lg[i2] - mx) / s;
    float dn = p1 + p2 + 1e-9f;
    g_wk[2*t + 0] = p1 / dn;
    g_wk[2*t + 1] = p2 / dn;
    int s1 = atomicAdd(&g_cnt[i1], 1); g_list[i1*Tt + s1] = 2*t + 0;
    int s2 = atomicAdd(&g_cnt[i2], 1); g_list[i2*Tt + s2] = 2*t + 1;
}

__global__ void __launch_bounds__(256)
final_ln_kernel(const float* __restrict__ gam, const float* __restrict__ bet,
                float* __restrict__ out)
{
    const int t = blockIdx.x, tid = threadIdx.x;
    const float w0 = g_wk[2*t], w1 = g_wk[2*t + 1];
    float vv[2];
    #pragma unroll
    for (int i = 0; i < 2; i++) {
        int d = tid + i*256;
        float moe = w0 * g_y[(long long)(2*t)   * Dm + d]
                  + w1 * g_y[(long long)(2*t+1) * Dm + d];
        moe = __bfloat162float(__float2bfloat16(moe));
        vv[i] = g_gen[(long long)t*Dm + d] + moe + g_x1[(long long)t*Dm + d];
    }
    float s = blockReduceSum256(vv[0] + vv[1]);
    float mean = s * (1.0f / Dm);
    float d0 = vv[0] - mean, d1 = vv[1] - mean;
    float sq = blockReduceSum256(d0*d0 + d1*d1);
    float rstd = rsqrtf(sq * (1.0f / Dm) + 1e-5f);
    out[(long long)t*Dm + tid]       = d0 * rstd * gam[tid]       + bet[tid];
    out[(long long)t*Dm + tid + 256] = d1 * rstd * gam[tid + 256] + bet[tid + 256];
}

// ------------------------------- launch -------------------------------------
extern "C" void kernel_launch(void* const* d_in, const int* in_sizes, int n_in,
                              void* d_out, int out_size)
{
    const float* x    = (const float*)d_in[0];
    const float* Wq   = (const float*)d_in[1];
    const float* bq   = (const float*)d_in[2];
    const float* Wk   = (const float*)d_in[3];
    const float* bk   = (const float*)d_in[4];
    const float* Wv   = (const float*)d_in[5];
    const float* bv   = (const float*)d_in[6];
    const float* Wo   = (const float*)d_in[7];
    const float* bo   = (const float*)d_in[8];
    const float* ln1g = (const float*)d_in[9];
    const float* ln1b = (const float*)d_in[10];
    const float* gW1  = (const float*)d_in[11];
    const float* gb1  = (const float*)d_in[12];
    const float* gW2  = (const float*)d_in[13];
    const float* gb2  = (const float*)d_in[14];
    const float* eW1  = (const float*)d_in[15];
    const float* eb1  = (const float*)d_in[16];
    const float* eW2  = (const float*)d_in[17];
    const float* eb2  = (const float*)d_in[18];
    const float* geW1 = (const float*)d_in[19];
    const float* geb1 = (const float*)d_in[20];
    const float* geW2 = (const float*)d_in[21];
    const float* geb2 = (const float*)d_in[22];
    const float* ln2g = (const float*)d_in[23];
    const float* ln2b = (const float*)d_in[24];

    float* out  = (float*)d_out;
    float* attn = out + ATTN_OFF;
    float* loss = out + LOSS_OFF;

    float *pv, *ptmp, *px1, *pgh, *pgen;
    cudaGetSymbolAddress((void**)&pv,   g_v);
    cudaGetSymbolAddress((void**)&ptmp, g_tmp);
    cudaGetSymbolAddress((void**)&px1,  g_x1);
    cudaGetSymbolAddress((void**)&pgh,  g_gh);
    cudaGetSymbolAddress((void**)&pgen, g_gen);

    unsigned short *xh,*xl,*qh,*ql,*kh,*kl,*vth,*vtl,*ctxh,*ctxl,*gnh,*gnl;
    unsigned short *wqh,*wql,*wkh,*wkl,*wvh,*wvl,*woh,*wol,*gw1h,*gw1l;
    unsigned short *gew1h,*gew1l,*gew2h,*gew2l,*ew1h,*ew1l,*ew2h,*ew2l;
    cudaGetSymbolAddress((void**)&xh, s_xh);     cudaGetSymbolAddress((void**)&xl, s_xl);
    cudaGetSymbolAddress((void**)&qh, s_qh);     cudaGetSymbolAddress((void**)&ql, s_ql);
    cudaGetSymbolAddress((void**)&kh, s_kh);     cudaGetSymbolAddress((void**)&kl, s_kl);
    cudaGetSymbolAddress((void**)&vth, s_vth);   cudaGetSymbolAddress((void**)&vtl, s_vtl);
    cudaGetSymbolAddress((void**)&ctxh, s_ctxh); cudaGetSymbolAddress((void**)&ctxl, s_ctxl);
    cudaGetSymbolAddress((void**)&gnh, s_gnh);   cudaGetSymbolAddress((void**)&gnl, s_gnl);
    cudaGetSymbolAddress((void**)&wqh, s_wqh);   cudaGetSymbolAddress((void**)&wql, s_wql);
    cudaGetSymbolAddress((void**)&wkh, s_wkh);   cudaGetSymbolAddress((void**)&wkl, s_wkl);
    cudaGetSymbolAddress((void**)&wvh, s_wvh);   cudaGetSymbolAddress((void**)&wvl, s_wvl);
    cudaGetSymbolAddress((void**)&woh, s_woh);   cudaGetSymbolAddress((void**)&wol, s_wol);
    cudaGetSymbolAddress((void**)&gw1h, s_gw1h); cudaGetSymbolAddress((void**)&gw1l, s_gw1l);
    cudaGetSymbolAddress((void**)&gew1h, s_gew1h); cudaGetSymbolAddress((void**)&gew1l, s_gew1l);
    cudaGetSymbolAddress((void**)&gew2h, s_gew2h); cudaGetSymbolAddress((void**)&gew2l, s_gew2l);
    cudaGetSymbolAddress((void**)&ew1h, s_ew1h); cudaGetSymbolAddress((void**)&ew1l, s_ew1l);
    cudaGetSymbolAddress((void**)&ew2h, s_ew2h); cudaGetSymbolAddress((void**)&ew2l, s_ew2l);

    unsigned short *x1h, *x1l;
    cudaGetSymbolAddress((void**)&x1h, s_x1h);   cudaGetSymbolAddress((void**)&x1l, s_x1l);

    const int SMEM_G = NS * 2048 * 2 * 4;              // 65536 B
    const int SMEM_V = NS * (2048*2 + 1024*2) * 2;     // 49152 B

    // streams/events created on the first (uncaptured) correctness call,
    // reused verbatim during graph capture.
    static cudaStream_t st2 = nullptr, st3 = nullptr;
    static cudaEvent_t evFork, evK, evVT, evW, evX1, evG, evT, evE3;
    static bool init_done = false;
    if (!init_done) {
        cudaFuncSetAttribute(gemm_s<0,0>, cudaFuncAttributeMaxDynamicSharedMemorySize, SMEM_G);
        cudaFuncSetAttribute(gemm_s<0,1>, cudaFuncAttributeMaxDynamicSharedMemorySize, SMEM_G);
        cudaFuncSetAttribute(gemm_s<1,0>, cudaFuncAttributeMaxDynamicSharedMemorySize, SMEM_G);
        cudaFuncSetAttribute(gemm_s<1,1>, cudaFuncAttributeMaxDynamicSharedMemorySize, SMEM_G);
        cudaFuncSetAttribute(expert_s<0>, cudaFuncAttributeMaxDynamicSharedMemorySize, SMEM_G);
        cudaFuncSetAttribute(expert_s<1>, cudaFuncAttributeMaxDynamicSharedMemorySize, SMEM_G);
        cudaFuncSetAttribute(scores_s,    cudaFuncAttributeMaxDynamicSharedMemorySize, SMEM_G);
        cudaFuncSetAttribute(attnv_s,     cudaFuncAttributeMaxDynamicSharedMemorySize, SMEM_V);
        cudaStreamCreateWithFlags(&st2, cudaStreamNonBlocking);
        cudaStreamCreateWithFlags(&st3, cudaStreamNonBlocking);
        cudaEventCreateWithFlags(&evFork, cudaEventDisableTiming);
        cudaEventCreateWithFlags(&evK,    cudaEventDisableTiming);
        cudaEventCreateWithFlags(&evVT,   cudaEventDisableTiming);
        cudaEventCreateWithFlags(&evW,    cudaEventDisableTiming);
        cudaEventCreateWithFlags(&evX1,   cudaEventDisableTiming);
        cudaEventCreateWithFlags(&evG,    cudaEventDisableTiming);
        cudaEventCreateWithFlags(&evT,    cudaEventDisableTiming);
        cudaEventCreateWithFlags(&evE3,   cudaEventDisableTiming);
        init_done = true;
    }

    dim3 blk(256);
    cudaStream_t s0 = 0;

    // -------- input conversions needed by QKV (on s0) --------
    esplit_kernel<<<(Tt*Dm + 255)/256, blk, 0, s0>>>(x, xh, xl, Tt*Dm);
    wsplit_t_kernel<<<dim3(Dm/32, Dm/32, 1), blk, 0, s0>>>(Wq, wqh, wql, Dm, Dm);
    wsplit_t_kernel<<<dim3(Dm/32, Dm/32, 1), blk, 0, s0>>>(Wk, wkh, wkl, Dm, Dm);
    wsplit_t_kernel<<<dim3(Dm/32, Dm/32, 1), blk, 0, s0>>>(Wv, wvh, wvl, Dm, Dm);
    wsplit_t_kernel<<<dim3(Dm/32, Dm/32, 1), blk, 0, s0>>>(Wo, woh, wol, Dm, Dm);

    // fork: st2 and st3 join after input conversions
    cudaEventRecord(evFork, s0);
    cudaStreamWaitEvent(st2, evFork, 0);
    cudaStreamWaitEvent(st3, evFork, 0);

    // -------- QKV projections, concurrent on 3 streams --------
    gemm_s<0,1><<<dim3(Dm/128, Tt/128), blk, SMEM_G, s0>>>(xh, xl, wqh, wql, bq, nullptr, qh, ql, Dm, Dm);
    gemm_s<0,1><<<dim3(Dm/128, Tt/128), blk, SMEM_G, st2>>>(xh, xl, wkh, wkl, bk, nullptr, kh, kl, Dm, Dm);
    cudaEventRecord(evK, st2);
    gemm_s<0,0><<<dim3(Dm/128, Tt/128), blk, SMEM_G, st3>>>(xh, xl, wvh, wvl, bv, pv, nullptr, nullptr, Dm, Dm);
    // vT transpose stays on st3 (program-ordered after V GEMM); runs
    // concurrently with scores_s on s0, which doesn't need V.
    wsplit_t_kernel<<<dim3(Dm/32, Ls/32, Bb), blk, 0, st3>>>(pv, vth, vtl, Ls, Dm);
    cudaEventRecord(evVT, st3);

    // st2 (after K): convert gate/gen/expert weight planes, hidden under attention
    wsplit_t_kernel<<<dim3(Dm/32, Dm/32, 1), blk, 0, st2>>>(gW1, gw1h, gw1l, Dm, Dm);
    wsplit_t_kernel<<<dim3(Fd/32, Dm/32, 1), blk, 0, st2>>>(geW1, gew1h, gew1l, Dm, Fd);
    wsplit_t_kernel<<<dim3(Dm/32, Fd/32, 1), blk, 0, st2>>>(geW2, gew2h, gew2l, Fd, Dm);
    wsplit_t_kernel<<<dim3(Fd/32, Dm/32, Ee), blk, 0, st2>>>(eW1, ew1h, ew1l, Dm, Fd);
    wsplit_t_kernel<<<dim3(Dm/32, Fd/32, Ee), blk, 0, st2>>>(eW2, ew2h, ew2l, Fd, Dm);
    cudaEventRecord(evW, st2);

    // -------- attention (s0): scores needs only q (s0) + k (evK) --------
    cudaStreamWaitEvent(s0, evK, 0);
    scores_s<<<dim3(Ls/128, Ls/128, Bb*Hh), blk, SMEM_G, s0>>>(attn);
    softmax_kernel<<<Bb*Hh*Ls, blk, 0, s0>>>(attn);
    cudaStreamWaitEvent(s0, evVT, 0);
    attnv_s<<<dim3(1, Ls/128, Bb*Hh), blk, SMEM_V, s0>>>();
    gemm_s<0,0><<<dim3(Dm/128, Tt/128), blk, SMEM_G, s0>>>(ctxh, ctxl, woh, wol, bo, ptmp, nullptr, nullptr, Dm, Dm);
    add_ln_kernel<<<Tt, blk, 0, s0>>>(x, ptmp, ln1g, ln1b, px1);
    cudaEventRecord(evX1, s0);

    // -------- general expert on st2, overlapped with routing path ----------
    cudaStreamWaitEvent(st2, evX1, 0);
    gemm_s<1,1><<<dim3(Fd/128, Tt/128), blk, SMEM_G, st2>>>(x1h, x1l, gew1h, gew1l, geb1, nullptr, gnh, gnl, Fd, Dm);
    gemm_s<0,0><<<dim3(Dm/128, Tt/128), blk, SMEM_G, st2>>>(gnh, gnl, gew2h, gew2l, geb2, pgen, nullptr, nullptr, Dm, Fd);
    cudaEventRecord(evG, st2);

    // -------- gate + routing on s0 --------
    cudaStreamWaitEvent(s0, evW, 0);
    gemm_s<1,0><<<dim3(Dm/128, Tt/128), blk, SMEM_G, s0>>>(x1h, x1l, gw1h, gw1l, gb1, pgh, nullptr, nullptr, Dm, Dm);
    gate_logits_kernel<<<Tt/32, blk, 0, s0>>>(gW2, gb2);
    init_kernel<<<1, 32, 0, s0>>>(loss);
    topk_kernel<<<Tt/256, blk, 0, s0>>>();
    cudaEventRecord(evT, s0);

    // -------- routed experts: two batched halves on two streams -----------
    // expert entry sets are disjoint -> cross-half writes are race-free.
    cudaStreamWaitEvent(st3, evT, 0);
    expert_s<0><<<dim3(Fd/128, Tt/128, Ee/2), blk, SMEM_G, s0>>>(ew1h, ew1l, eb1, 0);
    expert_s<1><<<dim3(Dm/128, Tt/128, Ee/2), blk, SMEM_G, s0>>>(ew2h, ew2l, eb2, 0);
    expert_s<0><<<dim3(Fd/128, Tt/128, Ee/2), blk, SMEM_G, st3>>>(ew1h, ew1l, eb1, Ee/2);
    expert_s<1><<<dim3(Dm/128, Tt/128, Ee/2), blk, SMEM_G, st3>>>(ew2h, ew2l, eb2, Ee/2);
    cudaEventRecord(evE3, st3);

    // -------- join + combine + LN2 --------
    cudaStreamWaitEvent(s0, evE3, 0);
    cudaStreamWaitEvent(s0, evG, 0);
    final_ln_kernel<<<Tt, blk, 0, s0>>>(ln2g, ln2b, out);
}

// round 16
// speedup vs baseline: 1.0933x; 1.0018x over previous
#include <cuda_runtime.h>
#include <cuda_bf16.h>
#include <cstdint>

// ---------------------------------------------------------------------------
// MoEEncoderLayer: B=2 L=2048 D=512 H=8 E=8 K=2 DF=2048
// Output layout in d_out (float32): [out: T*D][attn: B*H*L*L][aug_loss: 1]
// bf16x3 split-precision mma.sync m16n8k16; operands pre-split into bf16
// hi/lo planes; GEMM mainloop = cp.async + ldmatrix + mma (k16, NS=4).
// Streams as in R13. This round: vectorized softmax/esplit memory paths
// (float4 / uint4 accesses, contiguous per-thread element ownership).
// ---------------------------------------------------------------------------

#define Bb 2
#define Ls 2048
#define Dm 512
#define Hh 8
#define Ee 8
#define KTOP 2
#define Fd 2048
#define Hd 64
#define Tt (Bb*Ls)                      // 4096
#define NS 4                            // pipeline stages

static const long long ATTN_OFF = (long long)Tt * Dm;                      // 2097152
static const long long LOSS_OFF = ATTN_OFF + (long long)Bb*Hh*Ls*Ls;       // 69206016

// ------------------------- scratch (device globals) ------------------------
__device__ float g_v[Tt*Dm];
__device__ float g_tmp[Tt*Dm];
__device__ float g_x1[Tt*Dm];
__device__ float g_gh[Tt*Dm];
__device__ float g_logits[Tt*Ee];
__device__ float g_wk[Tt*KTOP];
__device__ int   g_cnt[Ee];
__device__ int   g_list[Ee*Tt];
__device__ float g_y[Tt*KTOP*Dm];
__device__ float g_gen[Tt*Dm];

// split planes (bf16 bits as ushort)
__device__ unsigned short s_xh[Tt*Dm],   s_xl[Tt*Dm];
__device__ unsigned short s_qh[Tt*Dm],   s_ql[Tt*Dm];
__device__ unsigned short s_kh[Tt*Dm],   s_kl[Tt*Dm];
__device__ unsigned short s_vth[Tt*Dm],  s_vtl[Tt*Dm];     // vT [Bb][Dm][Ls]
__device__ unsigned short s_ctxh[Tt*Dm], s_ctxl[Tt*Dm];
__device__ unsigned short s_x1h[Tt*Dm],  s_x1l[Tt*Dm];
__device__ unsigned short s_ehh[Tt*KTOP*Fd], s_ehl[Tt*KTOP*Fd];
__device__ unsigned short s_gnh[Tt*Fd],  s_gnl[Tt*Fd];
__device__ unsigned short s_ph[(long long)Bb*Hh*Ls*Ls];
__device__ unsigned short s_pl[(long long)Bb*Hh*Ls*Ls];
// weight planes, transposed to [N x K]
__device__ unsigned short s_wqh[Dm*Dm], s_wql[Dm*Dm];
__device__ unsigned short s_wkh[Dm*Dm], s_wkl[Dm*Dm];
__device__ unsigned short s_wvh[Dm*Dm], s_wvl[Dm*Dm];
__device__ unsigned short s_woh[Dm*Dm], s_wol[Dm*Dm];
__device__ unsigned short s_gw1h[Dm*Dm], s_gw1l[Dm*Dm];
__device__ unsigned short s_gew1h[Fd*Dm], s_gew1l[Fd*Dm];
__device__ unsigned short s_gew2h[Dm*Fd], s_gew2l[Dm*Fd];
__device__ unsigned short s_ew1h[Ee*Fd*Dm], s_ew1l[Ee*Fd*Dm];
__device__ unsigned short s_ew2h[Ee*Dm*Fd], s_ew2l[Ee*Dm*Fd];

// ------------------------------- helpers -----------------------------------
__device__ __forceinline__ float gelu_tanh(float x) {
    float x3 = x * x * x;
    float t  = tanhf(0.7978845608028654f * (x + 0.044715f * x3));
    return 0.5f * x * (1.0f + t);
}
__device__ __forceinline__ void bsplit(float x, unsigned short& h, unsigned short& l) {
    __nv_bfloat16 hb = __float2bfloat16_rn(x);
    float hf = __bfloat162float(hb);
    __nv_bfloat16 lb = __float2bfloat16_rn(x - hf);
    h = __bfloat16_as_ushort(hb);
    l = __bfloat16_as_ushort(lb);
}
__device__ __forceinline__ void bsplit2(float x0, float x1, uint32_t& hp, uint32_t& lp) {
    unsigned short h0, l0, h1, l1;
    bsplit(x0, h0, l0);
    bsplit(x1, h1, l1);
    hp = (uint32_t)h0 | ((uint32_t)h1 << 16);
    lp = (uint32_t)l0 | ((uint32_t)l1 << 16);
}
__device__ __forceinline__ void mma16(float* c, const uint32_t* a, const uint32_t* b) {
    asm volatile(
        "mma.sync.aligned.m16n8k16.row.col.f32.bf16.bf16.f32 "
        "{%0,%1,%2,%3}, {%4,%5,%6,%7}, {%8,%9}, {%0,%1,%2,%3};"
        : "+f"(c[0]), "+f"(c[1]), "+f"(c[2]), "+f"(c[3])
        : "r"(a[0]), "r"(a[1]), "r"(a[2]), "r"(a[3]), "r"(b[0]), "r"(b[1]));
}
__device__ __forceinline__ void ldsm4(uint32_t* d, uint32_t addr) {
    asm volatile("ldmatrix.sync.aligned.m8n8.x4.shared.b16 {%0,%1,%2,%3}, [%4];"
        : "=r"(d[0]), "=r"(d[1]), "=r"(d[2]), "=r"(d[3]) : "r"(addr));
}
__device__ __forceinline__ void cpa16(uint32_t dst, const void* src, bool pred) {
    int sz = pred ? 16 : 0;
    asm volatile("cp.async.cg.shared.global [%0], [%1], 16, %2;\n"
        :: "r"(dst), "l"(src), "r"(sz));
}
__device__ __forceinline__ void cpa_commit() { asm volatile("cp.async.commit_group;"); }
template<int N> __device__ __forceinline__ void cpa_wait() {
    asm volatile("cp.async.wait_group %0;" :: "n"(N));
}
__device__ __forceinline__ int swz8(int row, int khalf) {
    return row * 16 + ((khalf ^ ((row >> 2) & 1)) << 3);
}

__device__ __forceinline__ float warpReduceSum(float v) {
    #pragma unroll
    for (int o = 16; o > 0; o >>= 1) v += __shfl_xor_sync(0xffffffffu, v, o);
    return v;
}
__device__ __forceinline__ float warpReduceMax(float v) {
    #pragma unroll
    for (int o = 16; o > 0; o >>= 1) v = fmaxf(v, __shfl_xor_sync(0xffffffffu, v, o));
    return v;
}
__device__ __forceinline__ float blockReduceSum256(float v) {
    __shared__ float sh[33];
    int tid = threadIdx.x, lane = tid & 31, wid = tid >> 5;
    v = warpReduceSum(v);
    if (lane == 0) sh[wid] = v;
    __syncthreads();
    if (tid < 8) {
        float x = sh[tid];
        #pragma unroll
        for (int o = 4; o > 0; o >>= 1) x += __shfl_xor_sync(0xffu, x, o);
        if (tid == 0) sh[32] = x;
    }
    __syncthreads();
    float r = sh[32];
    __syncthreads();
    return r;
}
__device__ __forceinline__ float blockReduceMax256(float v) {
    __shared__ float sh[33];
    int tid = threadIdx.x, lane = tid & 31, wid = tid >> 5;
    v = warpReduceMax(v);
    if (lane == 0) sh[wid] = v;
    __syncthreads();
    if (tid < 8) {
        float x = sh[tid];
        #pragma unroll
        for (int o = 4; o > 0; o >>= 1) x = fmaxf(x, __shfl_xor_sync(0xffu, x, o));
        if (tid == 0) sh[32] = x;
    }
    __syncthreads();
    float r = sh[32];
    __syncthreads();
    return r;
}

#define SPLIT_MMA(ACC0, ACC1, AH, AL, BH, BL)                             \
    mma16(ACC0, AH[0], BH); mma16(ACC1, AH[1], BH);                        \
    mma16(ACC0, AL[0], BH); mma16(ACC1, AL[1], BH);                        \
    mma16(ACC0, AH[0], BL); mma16(ACC1, AH[1], BL);

// ======================= conversion kernels ================================
// vectorized: 4 elems/thread, float4 in, uint2 planes out
__global__ void __launch_bounds__(256)
esplit_kernel(const float* __restrict__ in, unsigned short* __restrict__ oh,
              unsigned short* __restrict__ ol, int n)
{
    int i = (blockIdx.x * 256 + threadIdx.x) * 4;
    if (i < n) {
        float4 v = *(const float4*)(in + i);
        uint32_t h0, l0, h1, l1;
        bsplit2(v.x, v.y, h0, l0);
        bsplit2(v.z, v.w, h1, l1);
        *(uint2*)&oh[i] = make_uint2(h0, h1);
        *(uint2*)&ol[i] = make_uint2(l0, l1);
    }
}

// in [K x N] fp32 (batched) -> planes [N x K] bf16 hi/lo (batched)
__global__ void __launch_bounds__(256)
wsplit_t_kernel(const float* __restrict__ in, unsigned short* __restrict__ oh,
                unsigned short* __restrict__ ol, int K, int N)
{
    __shared__ float t[32][33];
    long long base = (long long)blockIdx.z * K * N;
    int n0 = blockIdx.x * 32, k0 = blockIdx.y * 32;
    int tx = threadIdx.x & 31, ty = threadIdx.x >> 5;   // (32, 8)
    #pragma unroll
    for (int i = 0; i < 4; i++)
        t[ty + i*8][tx] = in[base + (long long)(k0 + ty + i*8) * N + n0 + tx];
    __syncthreads();
    #pragma unroll
    for (int i = 0; i < 4; i++) {
        unsigned short h, l;
        bsplit(t[tx][ty + i*8], h, l);
        long long o = base + (long long)(n0 + ty + i*8) * K + k0 + tx;
        oh[o] = h; ol[o] = l;
    }
}

// ===================== generic GEMM (pre-split planes) ======================
// C = act(A @ W + bias); A planes [M x Kd]; B planes [N x Kd] (pre-transposed)
// OMODE: 0 = fp32 C, 1 = split planes C
template<int ACT, int OMODE>
__global__ void __launch_bounds__(256)
gemm_s(const unsigned short* __restrict__ Ahi, const unsigned short* __restrict__ Alo,
       const unsigned short* __restrict__ Bhi, const unsigned short* __restrict__ Blo,
       const float* __restrict__ bias, float* __restrict__ Cf,
       unsigned short* __restrict__ Chi, unsigned short* __restrict__ Clo,
       int N, int Kd)
{
    extern __shared__ unsigned short sm[];
    unsigned short* As_hi = sm;
    unsigned short* As_lo = sm + NS*2048;
    unsigned short* Bs_hi = sm + 2*NS*2048;
    unsigned short* Bs_lo = sm + 3*NS*2048;

    const int tid = threadIdx.x, lane = tid & 31, wid = tid >> 5;
    const int g = lane >> 2, tg = lane & 3;
    const int wm = (wid & 3) * 32, wn = (wid >> 2) * 64;
    const int m0 = blockIdx.y * 128, n0 = blockIdx.x * 128;

    const int lm = tid >> 1, lkh = tid & 1;
    const int aso = swz8(lm, lkh);

    const unsigned short* Ah = Ahi + (long long)(m0 + lm) * Kd + lkh * 8;
    const unsigned short* Al = Alo + (long long)(m0 + lm) * Kd + lkh * 8;
    const unsigned short* Bh = Bhi + (long long)(n0 + lm) * Kd + lkh * 8;
    const unsigned short* Bl = Blo + (long long)(n0 + lm) * Kd + lkh * 8;

    const uint32_t aHiS = (uint32_t)__cvta_generic_to_shared(As_hi) + aso*2;
    const uint32_t aLoS = (uint32_t)__cvta_generic_to_shared(As_lo) + aso*2;
    const uint32_t bHiS = (uint32_t)__cvta_generic_to_shared(Bs_hi) + aso*2;
    const uint32_t bLoS = (uint32_t)__cvta_generic_to_shared(Bs_lo) + aso*2;

    const int rA = wm + ((lane >> 3) & 1) * 8 + (lane & 7);
    const uint32_t aOff = (uint32_t)(swz8(rA, (lane >> 4) & 1) * 2);
    const int cB = wn + ((lane >> 4) & 1) * 8 + (lane & 7);
    const uint32_t bOff = (uint32_t)(swz8(cB, (lane >> 3) & 1) * 2);
    const uint32_t aHiB = (uint32_t)__cvta_generic_to_shared(As_hi) + aOff;
    const uint32_t aLoB = (uint32_t)__cvta_generic_to_shared(As_lo) + aOff;
    const uint32_t bHiB = (uint32_t)__cvta_generic_to_shared(Bs_hi) + bOff;
    const uint32_t bLoB = (uint32_t)__cvta_generic_to_shared(Bs_lo) + bOff;

    float acc[2][8][4];
    #pragma unroll
    for (int i = 0; i < 2; i++)
        #pragma unroll
        for (int j = 0; j < 8; j++)
            #pragma unroll
            for (int q = 0; q < 4; q++) acc[i][j][q] = 0.f;

    const int nit = Kd / 16;
    #define G_ISSUE(s, k0v) { uint32_t o = (uint32_t)(s)*4096;              \
        cpa16(aHiS + o, Ah + (k0v), true); cpa16(aLoS + o, Al + (k0v), true);\
        cpa16(bHiS + o, Bh + (k0v), true); cpa16(bLoS + o, Bl + (k0v), true);\
        cpa_commit(); }

    #pragma unroll
    for (int s = 0; s < NS-1; s++) if (s < nit) G_ISSUE(s, s*16);

    for (int it = 0; it < nit; it++) {
        cpa_wait<NS-2>();
        __syncthreads();
        const uint32_t st = (uint32_t)(it & (NS-1)) * 4096;
        uint32_t ah[2][4], al[2][4];
        ldsm4(ah[0], aHiB + st);  ldsm4(ah[1], aHiB + st + 512);
        ldsm4(al[0], aLoB + st);  ldsm4(al[1], aLoB + st + 512);
        #pragma unroll
        for (int p = 0; p < 4; p++) {
            uint32_t bh[4], bl[4];
            ldsm4(bh, bHiB + st + p * 512);
            ldsm4(bl, bLoB + st + p * 512);
            SPLIT_MMA(acc[0][2*p],   acc[1][2*p],   ah, al, (bh + 0), (bl + 0));
            SPLIT_MMA(acc[0][2*p+1], acc[1][2*p+1], ah, al, (bh + 2), (bl + 2));
        }
        int nxt = it + NS - 1;
        if (nxt < nit) { G_ISSUE(nxt & (NS-1), nxt*16); } else { cpa_commit(); }
    }
    #undef G_ISSUE

    #pragma unroll
    for (int mi = 0; mi < 2; mi++) {
        const int r0 = m0 + wm + mi * 16 + g;
        #pragma unroll
        for (int nj = 0; nj < 8; nj++) {
            const int c = n0 + wn + nj * 8 + tg * 2;
            const float b0v = bias[c], b1v = bias[c + 1];
            float v0 = acc[mi][nj][0] + b0v, v1 = acc[mi][nj][1] + b1v;
            float v2 = acc[mi][nj][2] + b0v, v3 = acc[mi][nj][3] + b1v;
            if (ACT) { v0 = gelu_tanh(v0); v1 = gelu_tanh(v1); v2 = gelu_tanh(v2); v3 = gelu_tanh(v3); }
            if (OMODE == 0) {
                *(float2*)&Cf[(long long)r0 * N + c]       = make_float2(v0, v1);
                *(float2*)&Cf[(long long)(r0 + 8) * N + c] = make_float2(v2, v3);
            } else {
                uint32_t hp, lp;
                bsplit2(v0, v1, hp, lp);
                *(uint32_t*)&Chi[(long long)r0 * N + c] = hp;
                *(uint32_t*)&Clo[(long long)r0 * N + c] = lp;
                bsplit2(v2, v3, hp, lp);
                *(uint32_t*)&Chi[(long long)(r0 + 8) * N + c] = hp;
                *(uint32_t*)&Clo[(long long)(r0 + 8) * N + c] = lp;
            }
        }
    }
}

// ==================  gathered expert GEMMs (batched, e-offset) ==============
// MODE 0: eh[ent] = gelu(x1[ent>>1] @ eW1[e] + eb1[e])   (N=Fd, Kd=Dm)
// MODE 1: y[ent]  = eh[ent] @ eW2[e] + eb2[e]            (N=Dm, Kd=Fd)
// e = e0 + blockIdx.z (half-split: two launches of z-dim Ee/2)
template<int MODE>
__global__ void __launch_bounds__(256)
expert_s(const unsigned short* __restrict__ Whi, const unsigned short* __restrict__ Wlo,
         const float* __restrict__ bias, const int e0)
{
    const int e = e0 + blockIdx.z;
    const int cnt = g_cnt[e];
    const int r0blk = blockIdx.y * 128;
    if (r0blk >= cnt) return;

    const int N  = MODE ? Dm : Fd;
    const int Kd = MODE ? Fd : Dm;

    extern __shared__ unsigned short sm[];
    unsigned short* As_hi = sm;
    unsigned short* As_lo = sm + NS*2048;
    unsigned short* Bs_hi = sm + 2*NS*2048;
    unsigned short* Bs_lo = sm + 3*NS*2048;
    __shared__ int toks[128];

    const int tid = threadIdx.x, lane = tid & 31, wid = tid >> 5;
    const int g = lane >> 2, tg = lane & 3;
    const int wm = (wid & 3) * 32, wn = (wid >> 2) * 64;
    const int n0 = blockIdx.x * 128;

    if (tid < 128) {
        int r = r0blk + tid;
        toks[tid] = (r < cnt) ? g_list[e * Tt + r] : -1;
    }
    __syncthreads();

    const int lm = tid >> 1, lkh = tid & 1;
    const int aso = swz8(lm, lkh);

    const int entA = toks[lm];
    const bool apred = (entA >= 0);
    long long arow = apred ? (MODE ? (long long)entA : (long long)(entA >> 1)) : 0;
    const unsigned short* Ahp = (MODE ? s_ehh : s_x1h) + arow * Kd + lkh * 8;
    const unsigned short* Alp = (MODE ? s_ehl : s_x1l) + arow * Kd + lkh * 8;
    const unsigned short* Bhp = Whi + (long long)e * Dm * Fd + (long long)(n0 + lm) * Kd + lkh * 8;
    const unsigned short* Blp = Wlo + (long long)e * Dm * Fd + (long long)(n0 + lm) * Kd + lkh * 8;
    const float* bp = bias + (long long)e * N;

    const uint32_t aHiS = (uint32_t)__cvta_generic_to_shared(As_hi) + aso*2;
    const uint32_t aLoS = (uint32_t)__cvta_generic_to_shared(As_lo) + aso*2;
    const uint32_t bHiS = (uint32_t)__cvta_generic_to_shared(Bs_hi) + aso*2;
    const uint32_t bLoS = (uint32_t)__cvta_generic_to_shared(Bs_lo) + aso*2;

    const int rA = wm + ((lane >> 3) & 1) * 8 + (lane & 7);
    const uint32_t aOff = (uint32_t)(swz8(rA, (lane >> 4) & 1) * 2);
    const int cB = wn + ((lane >> 4) & 1) * 8 + (lane & 7);
    const uint32_t bOff = (uint32_t)(swz8(cB, (lane >> 3) & 1) * 2);
    const uint32_t aHiB = (uint32_t)__cvta_generic_to_shared(As_hi) + aOff;
    const uint32_t aLoB = (uint32_t)__cvta_generic_to_shared(As_lo) + aOff;
    const uint32_t bHiB = (uint32_t)__cvta_generic_to_shared(Bs_hi) + bOff;
    const uint32_t bLoB = (uint32_t)__cvta_generic_to_shared(Bs_lo) + bOff;

    float acc[2][8][4];
    #pragma unroll
    for (int i = 0; i < 2; i++)
        #pragma unroll
        for (int j = 0; j < 8; j++)
            #pragma unroll
            for (int q = 0; q < 4; q++) acc[i][j][q] = 0.f;

    const int nit = Kd / 16;
    #define E_ISSUE(s, k0v) { uint32_t o = (uint32_t)(s)*4096;                 \
        cpa16(aHiS + o, Ahp + (k0v), apred); cpa16(aLoS + o, Alp + (k0v), apred);\
        cpa16(bHiS + o, Bhp + (k0v), true);  cpa16(bLoS + o, Blp + (k0v), true); \
        cpa_commit(); }

    #pragma unroll
    for (int s = 0; s < NS-1; s++) if (s < nit) E_ISSUE(s, s*16);

    for (int it = 0; it < nit; it++) {
        cpa_wait<NS-2>();
        __syncthreads();
        const uint32_t st = (uint32_t)(it & (NS-1)) * 4096;
        uint32_t ah[2][4], al[2][4];
        ldsm4(ah[0], aHiB + st);  ldsm4(ah[1], aHiB + st + 512);
        ldsm4(al[0], aLoB + st);  ldsm4(al[1], aLoB + st + 512);
        #pragma unroll
        for (int p = 0; p < 4; p++) {
            uint32_t bh[4], bl[4];
            ldsm4(bh, bHiB + st + p * 512);
            ldsm4(bl, bLoB + st + p * 512);
            SPLIT_MMA(acc[0][2*p],   acc[1][2*p],   ah, al, (bh + 0), (bl + 0));
            SPLIT_MMA(acc[0][2*p+1], acc[1][2*p+1], ah, al, (bh + 2), (bl + 2));
        }
        int nxt = it + NS - 1;
        if (nxt < nit) { E_ISSUE(nxt & (NS-1), nxt*16); } else { cpa_commit(); }
    }
    #undef E_ISSUE

    #pragma unroll
    for (int mi = 0; mi < 2; mi++) {
        const int rr0 = wm + mi * 16 + g;
        const int ent0 = toks[rr0], ent1 = toks[rr0 + 8];
        #pragma unroll
        for (int nj = 0; nj < 8; nj++) {
            const int c = wn + nj * 8 + tg * 2;
            const float b0v = bp[n0 + c], b1v = bp[n0 + c + 1];
            if (ent0 >= 0) {
                float v0 = acc[mi][nj][0] + b0v, v1 = acc[mi][nj][1] + b1v;
                if (MODE == 0) {
                    v0 = gelu_tanh(v0); v1 = gelu_tanh(v1);
                    uint32_t hp, lp;
                    bsplit2(v0, v1, hp, lp);
                    *(uint32_t*)&s_ehh[(long long)ent0 * Fd + n0 + c] = hp;
                    *(uint32_t*)&s_ehl[(long long)ent0 * Fd + n0 + c] = lp;
                } else {
                    *(float2*)&g_y[(long long)ent0 * Dm + n0 + c] = make_float2(v0, v1);
                }
            }
            if (ent1 >= 0) {
                float v2 = acc[mi][nj][2] + b0v, v3 = acc[mi][nj][3] + b1v;
                if (MODE == 0) {
                    v2 = gelu_tanh(v2); v3 = gelu_tanh(v3);
                    uint32_t hp, lp;
                    bsplit2(v2, v3, hp, lp);
                    *(uint32_t*)&s_ehh[(long long)ent1 * Fd + n0 + c] = hp;
                    *(uint32_t*)&s_ehl[(long long)ent1 * Fd + n0 + c] = lp;
                } else {
                    *(float2*)&g_y[(long long)ent1 * Dm + n0 + c] = make_float2(v2, v3);
                }
            }
        }
    }
}

// ================  attention scores: Q K^T / 8  =============================
__global__ void __launch_bounds__(256)
scores_s(float* __restrict__ attn)
{
    extern __shared__ unsigned short sm[];
    unsigned short* As_hi = sm;
    unsigned short* As_lo = sm + NS*2048;
    unsigned short* Bs_hi = sm + 2*NS*2048;
    unsigned short* Bs_lo = sm + 3*NS*2048;

    const int tid = threadIdx.x, lane = tid & 31, wid = tid >> 5;
    const int g = lane >> 2, tg = lane & 3;
    const int wm = (wid & 3) * 32, wn = (wid >> 2) * 64;
    const int bh_ = blockIdx.z; const int b = bh_ >> 3, h = bh_ & 7;
    const int i0 = blockIdx.y * 128, j0 = blockIdx.x * 128;

    const int lm = tid >> 1, lkh = tid & 1;
    const int aso = swz8(lm, lkh);

    const unsigned short* Ah = s_qh + (long long)(b*Ls + i0 + lm) * Dm + h*Hd + lkh*8;
    const unsigned short* Al = s_ql + (long long)(b*Ls + i0 + lm) * Dm + h*Hd + lkh*8;
    const unsigned short* Bh = s_kh + (long long)(b*Ls + j0 + lm) * Dm + h*Hd + lkh*8;
    const unsigned short* Bl = s_kl + (long long)(b*Ls + j0 + lm) * Dm + h*Hd + lkh*8;

    const uint32_t aHiS = (uint32_t)__cvta_generic_to_shared(As_hi) + aso*2;
    const uint32_t aLoS = (uint32_t)__cvta_generic_to_shared(As_lo) + aso*2;
    const uint32_t bHiS = (uint32_t)__cvta_generic_to_shared(Bs_hi) + aso*2;
    const uint32_t bLoS = (uint32_t)__cvta_generic_to_shared(Bs_lo) + aso*2;

    const int rA = wm + ((lane >> 3) & 1) * 8 + (lane & 7);
    const uint32_t aOff = (uint32_t)(swz8(rA, (lane >> 4) & 1) * 2);
    const int cB = wn + ((lane >> 4) & 1) * 8 + (lane & 7);
    const uint32_t bOff = (uint32_t)(swz8(cB, (lane >> 3) & 1) * 2);
    const uint32_t aHiB = (uint32_t)__cvta_generic_to_shared(As_hi) + aOff;
    const uint32_t aLoB = (uint32_t)__cvta_generic_to_shared(As_lo) + aOff;
    const uint32_t bHiB = (uint32_t)__cvta_generic_to_shared(Bs_hi) + bOff;
    const uint32_t bLoB = (uint32_t)__cvta_generic_to_shared(Bs_lo) + bOff;

    float acc[2][8][4];
    #pragma unroll
    for (int i = 0; i < 2; i++)
        #pragma unroll
        for (int j = 0; j < 8; j++)
            #pragma unroll
            for (int q2 = 0; q2 < 4; q2++) acc[i][j][q2] = 0.f;

    const int nit = Hd / 16;   // 4
    #define S_ISSUE(s, k0v) { uint32_t o = (uint32_t)(s)*4096;              \
        cpa16(aHiS + o, Ah + (k0v), true); cpa16(aLoS + o, Al + (k0v), true);\
        cpa16(bHiS + o, Bh + (k0v), true); cpa16(bLoS + o, Bl + (k0v), true);\
        cpa_commit(); }

    #pragma unroll
    for (int s = 0; s < NS-1; s++) if (s < nit) S_ISSUE(s, s*16);

    for (int it = 0; it < nit; it++) {
        cpa_wait<NS-2>();
        __syncthreads();
        const uint32_t st = (uint32_t)(it & (NS-1)) * 4096;
        uint32_t ah[2][4], al[2][4];
        ldsm4(ah[0], aHiB + st);  ldsm4(ah[1], aHiB + st + 512);
        ldsm4(al[0], aLoB + st);  ldsm4(al[1], aLoB + st + 512);
        #pragma unroll
        for (int p = 0; p < 4; p++) {
            uint32_t bh2[4], bl2[4];
            ldsm4(bh2, bHiB + st + p * 512);
            ldsm4(bl2, bLoB + st + p * 512);
            SPLIT_MMA(acc[0][2*p],   acc[1][2*p],   ah, al, (bh2 + 0), (bl2 + 0));
            SPLIT_MMA(acc[0][2*p+1], acc[1][2*p+1], ah, al, (bh2 + 2), (bl2 + 2));
        }
        int nxt = it + NS - 1;
        if (nxt < nit) { S_ISSUE(nxt & (NS-1), nxt*16); } else { cpa_commit(); }
    }
    #undef S_ISSUE

    float* O = attn + (long long)bh_ * Ls * Ls;
    #pragma unroll
    for (int mi = 0; mi < 2; mi++) {
        const int r0 = i0 + wm + mi * 16 + g;
        #pragma unroll
        for (int nj = 0; nj < 8; nj++) {
            const int c = j0 + wn + nj * 8 + tg * 2;
            *(float2*)&O[(long long)r0 * Ls + c] =
                make_float2(acc[mi][nj][0] * 0.125f, acc[mi][nj][1] * 0.125f);
            *(float2*)&O[(long long)(r0 + 8) * Ls + c] =
                make_float2(acc[mi][nj][2] * 0.125f, acc[mi][nj][3] * 0.125f);
        }
    }
}

// =====================  P @ V  ==============================================
// grid = (1, L/128, B*H).  Block 128x64, warp 32x32, Kd = L = 2048.
__global__ void __launch_bounds__(256)
attnv_s()
{
    extern __shared__ unsigned short sm[];
    unsigned short* As_hi = sm;                 // NS*2048
    unsigned short* As_lo = sm + NS*2048;
    unsigned short* Bs_hi = sm + 2*NS*2048;     // NS*1024
    unsigned short* Bs_lo = sm + 2*NS*2048 + NS*1024;

    const int tid = threadIdx.x, lane = tid & 31, wid = tid >> 5;
    const int g = lane >> 2, tg = lane & 3;
    const int wm = (wid & 3) * 32, wn = (wid >> 2) * 32;
    const int bh_ = blockIdx.z; const int b = bh_ >> 3, h = bh_ & 7;
    const int i0 = blockIdx.y * 128;

    const int lm = tid >> 1, lkh = tid & 1;
    const int aso = swz8(lm, lkh);
    const int blm = lm & 63;
    const bool bpred = tid < 128;
    const int bso = swz8(blm, lkh);

    const unsigned short* Ah = s_ph + (long long)bh_ * Ls * Ls + (long long)(i0 + lm) * Ls + lkh*8;
    const unsigned short* Al = s_pl + (long long)bh_ * Ls * Ls + (long long)(i0 + lm) * Ls + lkh*8;
    const unsigned short* Bh = s_vth + ((long long)b * Dm + h * Hd + blm) * Ls + lkh*8;
    const unsigned short* Bl = s_vtl + ((long long)b * Dm + h * Hd + blm) * Ls + lkh*8;

    const uint32_t aHiS = (uint32_t)__cvta_generic_to_shared(As_hi) + aso*2;
    const uint32_t aLoS = (uint32_t)__cvta_generic_to_shared(As_lo) + aso*2;
    const uint32_t bHiS = (uint32_t)__cvta_generic_to_shared(Bs_hi) + bso*2;
    const uint32_t bLoS = (uint32_t)__cvta_generic_to_shared(Bs_lo) + bso*2;

    const int rA = wm + ((lane >> 3) & 1) * 8 + (lane & 7);
    const uint32_t aOff = (uint32_t)(swz8(rA, (lane >> 4) & 1) * 2);
    const int cB = wn + ((lane >> 4) & 1) * 8 + (lane & 7);
    const uint32_t bOff = (uint32_t)(swz8(cB, (lane >> 3) & 1) * 2);
    const uint32_t aHiB = (uint32_t)__cvta_generic_to_shared(As_hi) + aOff;
    const uint32_t aLoB = (uint32_t)__cvta_generic_to_shared(As_lo) + aOff;
    const uint32_t bHiB = (uint32_t)__cvta_generic_to_shared(Bs_hi) + bOff;
    const uint32_t bLoB = (uint32_t)__cvta_generic_to_shared(Bs_lo) + bOff;

    float acc[2][4][4];
    #pragma unroll
    for (int i = 0; i < 2; i++)
        #pragma unroll
        for (int j = 0; j < 4; j++)
            #pragma unroll
            for (int q = 0; q < 4; q++) acc[i][j][q] = 0.f;

    const int nit = Ls / 16;   // 128
    // non-owning threads (tid>=128) must NOT issue the B copies at all:
    // cp.async with src-size 0 still zero-fills dst, racing the owners' data.
    #define V_ISSUE(s, k0v) {                                               \
        cpa16(aHiS + (uint32_t)(s)*4096, Ah + (k0v), true);                 \
        cpa16(aLoS + (uint32_t)(s)*4096, Al + (k0v), true);                 \
        if (bpred) {                                                        \
            cpa16(bHiS + (uint32_t)(s)*2048, Bh + (k0v), true);             \
            cpa16(bLoS + (uint32_t)(s)*2048, Bl + (k0v), true);             \
        }                                                                   \
        cpa_commit(); }

    #pragma unroll
    for (int s = 0; s < NS-1; s++) if (s < nit) V_ISSUE(s, s*16);

    for (int it = 0; it < nit; it++) {
        cpa_wait<NS-2>();
        __syncthreads();
        const uint32_t stA = (uint32_t)(it & (NS-1)) * 4096;
        const uint32_t stB = (uint32_t)(it & (NS-1)) * 2048;
        uint32_t ah[2][4], al[2][4];
        ldsm4(ah[0], aHiB + stA);  ldsm4(ah[1], aHiB + stA + 512);
        ldsm4(al[0], aLoB + stA);  ldsm4(al[1], aLoB + stA + 512);
        #pragma unroll
        for (int p = 0; p < 2; p++) {
            uint32_t bh2[4], bl2[4];
            ldsm4(bh2, bHiB + stB + p * 512);
            ldsm4(bl2, bLoB + stB + p * 512);
            SPLIT_MMA(acc[0][2*p],   acc[1][2*p],   ah, al, (bh2 + 0), (bl2 + 0));
            SPLIT_MMA(acc[0][2*p+1], acc[1][2*p+1], ah, al, (bh2 + 2), (bl2 + 2));
        }
        int nxt = it + NS - 1;
        if (nxt < nit) { V_ISSUE(nxt & (NS-1), nxt*16); } else { cpa_commit(); }
    }
    #undef V_ISSUE

    #pragma unroll
    for (int mi = 0; mi < 2; mi++) {
        const long long r0 = (long long)b * Ls + i0 + wm + mi * 16 + g;
        #pragma unroll
        for (int nj = 0; nj < 4; nj++) {
            const int c = h * Hd + wn + nj * 8 + tg * 2;
            uint32_t hp, lp;
            bsplit2(acc[mi][nj][0], acc[mi][nj][1], hp, lp);
            *(uint32_t*)&s_ctxh[r0 * Dm + c] = hp;
            *(uint32_t*)&s_ctxl[r0 * Dm + c] = lp;
            bsplit2(acc[mi][nj][2], acc[mi][nj][3], hp, lp);
            *(uint32_t*)&s_ctxh[(r0 + 8) * Dm + c] = hp;
            *(uint32_t*)&s_ctxl[(r0 + 8) * Dm + c] = lp;
        }
    }
}

// ======================== elementwise / small kernels =======================
// vectorized: 8 contiguous elems/thread, float4 I/O + uint4 plane stores
__global__ void __launch_bounds__(256)
softmax_kernel(float* __restrict__ attn)
{
    const long long row = blockIdx.x;
    float* p = attn + row * (long long)Ls;
    const int base = threadIdx.x * 8;
    float4 a0 = *(float4*)(p + base);
    float4 a1 = *(float4*)(p + base + 4);
    float v[8] = {a0.x, a0.y, a0.z, a0.w, a1.x, a1.y, a1.z, a1.w};
    float mx = v[0];
    #pragma unroll
    for (int i = 1; i < 8; i++) mx = fmaxf(mx, v[i]);
    mx = blockReduceMax256(mx);
    float s = 0.f;
    #pragma unroll
    for (int i = 0; i < 8; i++) { v[i] = __expf(v[i] - mx); s += v[i]; }
    s = blockReduceSum256(s);
    float inv = 1.f / s;
    #pragma unroll
    for (int i = 0; i < 8; i++) v[i] *= inv;
    *(float4*)(p + base)     = make_float4(v[0], v[1], v[2], v[3]);
    *(float4*)(p + base + 4) = make_float4(v[4], v[5], v[6], v[7]);
    uint32_t hp[4], lp[4];
    #pragma unroll
    for (int i = 0; i < 4; i++) bsplit2(v[2*i], v[2*i+1], hp[i], lp[i]);
    const long long idx = row * Ls + base;
    *(uint4*)&s_ph[idx] = make_uint4(hp[0], hp[1], hp[2], hp[3]);
    *(uint4*)&s_pl[idx] = make_uint4(lp[0], lp[1], lp[2], lp[3]);
}

__global__ void __launch_bounds__(256)
add_ln_kernel(const float* __restrict__ a, const float* __restrict__ b,
              const float* __restrict__ gam, const float* __restrict__ bet,
              float* __restrict__ out)
{
    const int t = blockIdx.x, tid = threadIdx.x;
    float v0 = a[(long long)t*Dm + tid]       + b[(long long)t*Dm + tid];
    float v1 = a[(long long)t*Dm + tid + 256] + b[(long long)t*Dm + tid + 256];
    float s = blockReduceSum256(v0 + v1);
    float mean = s * (1.0f / Dm);
    float d0 = v0 - mean, d1 = v1 - mean;
    float sq = blockReduceSum256(d0*d0 + d1*d1);
    float rstd = rsqrtf(sq * (1.0f / Dm) + 1e-5f);
    float o0 = d0 * rstd * gam[tid]       + bet[tid];
    float o1 = d1 * rstd * gam[tid + 256] + bet[tid + 256];
    out[(long long)t*Dm + tid]       = o0;
    out[(long long)t*Dm + tid + 256] = o1;
    unsigned short h, l;
    bsplit(o0, h, l); s_x1h[(long long)t*Dm + tid] = h;       s_x1l[(long long)t*Dm + tid] = l;
    bsplit(o1, h, l); s_x1h[(long long)t*Dm + tid + 256] = h; s_x1l[(long long)t*Dm + tid + 256] = l;
}

__global__ void __launch_bounds__(256)
gate_logits_kernel(const float* __restrict__ gW2, const float* __restrict__ gb2)
{
    const int t = blockIdx.x * 32 + (threadIdx.x >> 3);
    const int e = threadIdx.x & 7;
    const float* row = g_gh + (long long)t * Dm;
    float s = 0.f;
    #pragma unroll 8
    for (int d = 0; d < Dm; d++) s += row[d] * gW2[d*Ee + e];
    g_logits[t*Ee + e] = s + gb2[e];
}

__global__ void init_kernel(float* __restrict__ loss)
{
    if (threadIdx.x < Ee) g_cnt[threadIdx.x] = 0;
    if (threadIdx.x == 0) *loss = 0.0f;
}

__global__ void __launch_bounds__(256)
topk_kernel()
{
    const int t = blockIdx.x * 256 + threadIdx.x;
    if (t >= Tt) return;
    float lg[Ee];
    #pragma unroll
    for (int e = 0; e < Ee; e++) lg[e] = g_logits[t*Ee + e];
    int i1 = 0;
    #pragma unroll
    for (int e = 1; e < Ee; e++) if (lg[e] > lg[i1]) i1 = e;
    int i2 = -1;
    #pragma unroll
    for (int e = 0; e < Ee; e++) if (e != i1 && (i2 < 0 || lg[e] > lg[i2])) i2 = e;
    float mx = lg[i1];
    float s = 0.f;
    #pragma unroll
    for (int e = 0; e < Ee; e++) s += __expf(lg[e] - mx);
    float p1 = __expf(lg[i1] - mx) / s;
    float p2 = __expf(lg[i2] - mx) / s;
    float dn = p1 + p2 + 1e-9f;
    g_wk[2*t + 0] = p1 / dn;
    g_wk[2*t + 1] = p2 / dn;
    int s1 = atomicAdd(&g_cnt[i1], 1); g_list[i1*Tt + s1] = 2*t + 0;
    int s2 = atomicAdd(&g_cnt[i2], 1); g_list[i2*Tt + s2] = 2*t + 1;
}

__global__ void __launch_bounds__(256)
final_ln_kernel(const float* __restrict__ gam, const float* __restrict__ bet,
                float* __restrict__ out)
{
    const int t = blockIdx.x, tid = threadIdx.x;
    const float w0 = g_wk[2*t], w1 = g_wk[2*t + 1];
    float vv[2];
    #pragma unroll
    for (int i = 0; i < 2; i++) {
        int d = tid + i*256;
        float moe = w0 * g_y[(long long)(2*t)   * Dm + d]
                  + w1 * g_y[(long long)(2*t+1) * Dm + d];
        moe = __bfloat162float(__float2bfloat16(moe));
        vv[i] = g_gen[(long long)t*Dm + d] + moe + g_x1[(long long)t*Dm + d];
    }
    float s = blockReduceSum256(vv[0] + vv[1]);
    float mean = s * (1.0f / Dm);
    float d0 = vv[0] - mean, d1 = vv[1] - mean;
    float sq = blockReduceSum256(d0*d0 + d1*d1);
    float rstd = rsqrtf(sq * (1.0f / Dm) + 1e-5f);
    out[(long long)t*Dm + tid]       = d0 * rstd * gam[tid]       + bet[tid];
    out[(long long)t*Dm + tid + 256] = d1 * rstd * gam[tid + 256] + bet[tid + 256];
}

// ------------------------------- launch -------------------------------------
extern "C" void kernel_launch(void* const* d_in, const int* in_sizes, int n_in,
                              void* d_out, int out_size)
{
    const float* x    = (const float*)d_in[0];
    const float* Wq   = (const float*)d_in[1];
    const float* bq   = (const float*)d_in[2];
    const float* Wk   = (const float*)d_in[3];
    const float* bk   = (const float*)d_in[4];
    const float* Wv   = (const float*)d_in[5];
    const float* bv   = (const float*)d_in[6];
    const float* Wo   = (const float*)d_in[7];
    const float* bo   = (const float*)d_in[8];
    const float* ln1g = (const float*)d_in[9];
    const float* ln1b = (const float*)d_in[10];
    const float* gW1  = (const float*)d_in[11];
    const float* gb1  = (const float*)d_in[12];
    const float* gW2  = (const float*)d_in[13];
    const float* gb2  = (const float*)d_in[14];
    const float* eW1  = (const float*)d_in[15];
    const float* eb1  = (const float*)d_in[16];
    const float* eW2  = (const float*)d_in[17];
    const float* eb2  = (const float*)d_in[18];
    const float* geW1 = (const float*)d_in[19];
    const float* geb1 = (const float*)d_in[20];
    const float* geW2 = (const float*)d_in[21];
    const float* geb2 = (const float*)d_in[22];
    const float* ln2g = (const float*)d_in[23];
    const float* ln2b = (const float*)d_in[24];

    float* out  = (float*)d_out;
    float* attn = out + ATTN_OFF;
    float* loss = out + LOSS_OFF;

    float *pv, *ptmp, *px1, *pgh, *pgen;
    cudaGetSymbolAddress((void**)&pv,   g_v);
    cudaGetSymbolAddress((void**)&ptmp, g_tmp);
    cudaGetSymbolAddress((void**)&px1,  g_x1);
    cudaGetSymbolAddress((void**)&pgh,  g_gh);
    cudaGetSymbolAddress((void**)&pgen, g_gen);

    unsigned short *xh,*xl,*qh,*ql,*kh,*kl,*vth,*vtl,*ctxh,*ctxl,*gnh,*gnl;
    unsigned short *wqh,*wql,*wkh,*wkl,*wvh,*wvl,*woh,*wol,*gw1h,*gw1l;
    unsigned short *gew1h,*gew1l,*gew2h,*gew2l,*ew1h,*ew1l,*ew2h,*ew2l;
    cudaGetSymbolAddress((void**)&xh, s_xh);     cudaGetSymbolAddress((void**)&xl, s_xl);
    cudaGetSymbolAddress((void**)&qh, s_qh);     cudaGetSymbolAddress((void**)&ql, s_ql);
    cudaGetSymbolAddress((void**)&kh, s_kh);     cudaGetSymbolAddress((void**)&kl, s_kl);
    cudaGetSymbolAddress((void**)&vth, s_vth);   cudaGetSymbolAddress((void**)&vtl, s_vtl);
    cudaGetSymbolAddress((void**)&ctxh, s_ctxh); cudaGetSymbolAddress((void**)&ctxl, s_ctxl);
    cudaGetSymbolAddress((void**)&gnh, s_gnh);   cudaGetSymbolAddress((void**)&gnl, s_gnl);
    cudaGetSymbolAddress((void**)&wqh, s_wqh);   cudaGetSymbolAddress((void**)&wql, s_wql);
    cudaGetSymbolAddress((void**)&wkh, s_wkh);   cudaGetSymbolAddress((void**)&wkl, s_wkl);
    cudaGetSymbolAddress((void**)&wvh, s_wvh);   cudaGetSymbolAddress((void**)&wvl, s_wvl);
    cudaGetSymbolAddress((void**)&woh, s_woh);   cudaGetSymbolAddress((void**)&wol, s_wol);
    cudaGetSymbolAddress((void**)&gw1h, s_gw1h); cudaGetSymbolAddress((void**)&gw1l, s_gw1l);
    cudaGetSymbolAddress((void**)&gew1h, s_gew1h); cudaGetSymbolAddress((void**)&gew1l, s_gew1l);
    cudaGetSymbolAddress((void**)&gew2h, s_gew2h); cudaGetSymbolAddress((void**)&gew2l, s_gew2l);
    cudaGetSymbolAddress((void**)&ew1h, s_ew1h); cudaGetSymbolAddress((void**)&ew1l, s_ew1l);
    cudaGetSymbolAddress((void**)&ew2h, s_ew2h); cudaGetSymbolAddress((void**)&ew2l, s_ew2l);

    unsigned short *x1h, *x1l;
    cudaGetSymbolAddress((void**)&x1h, s_x1h);   cudaGetSymbolAddress((void**)&x1l, s_x1l);

    const int SMEM_G = NS * 2048 * 2 * 4;              // 65536 B
    const int SMEM_V = NS * (2048*2 + 1024*2) * 2;     // 49152 B

    // streams/events created on the first (uncaptured) correctness call,
    // reused verbatim during graph capture.
    static cudaStream_t st2 = nullptr, st3 = nullptr;
    static cudaEvent_t evFork, evK, evVT, evW, evX1, evG, evT, evE3;
    static bool init_done = false;
    if (!init_done) {
        cudaFuncSetAttribute(gemm_s<0,0>, cudaFuncAttributeMaxDynamicSharedMemorySize, SMEM_G);
        cudaFuncSetAttribute(gemm_s<0,1>, cudaFuncAttributeMaxDynamicSharedMemorySize, SMEM_G);
        cudaFuncSetAttribute(gemm_s<1,0>, cudaFuncAttributeMaxDynamicSharedMemorySize, SMEM_G);
        cudaFuncSetAttribute(gemm_s<1,1>, cudaFuncAttributeMaxDynamicSharedMemorySize, SMEM_G);
        cudaFuncSetAttribute(expert_s<0>, cudaFuncAttributeMaxDynamicSharedMemorySize, SMEM_G);
        cudaFuncSetAttribute(expert_s<1>, cudaFuncAttributeMaxDynamicSharedMemorySize, SMEM_G);
        cudaFuncSetAttribute(scores_s,    cudaFuncAttributeMaxDynamicSharedMemorySize, SMEM_G);
        cudaFuncSetAttribute(attnv_s,     cudaFuncAttributeMaxDynamicSharedMemorySize, SMEM_V);
        cudaStreamCreateWithFlags(&st2, cudaStreamNonBlocking);
        cudaStreamCreateWithFlags(&st3, cudaStreamNonBlocking);
        cudaEventCreateWithFlags(&evFork, cudaEventDisableTiming);
        cudaEventCreateWithFlags(&evK,    cudaEventDisableTiming);
        cudaEventCreateWithFlags(&evVT,   cudaEventDisableTiming);
        cudaEventCreateWithFlags(&evW,    cudaEventDisableTiming);
        cudaEventCreateWithFlags(&evX1,   cudaEventDisableTiming);
        cudaEventCreateWithFlags(&evG,    cudaEventDisableTiming);
        cudaEventCreateWithFlags(&evT,    cudaEventDisableTiming);
        cudaEventCreateWithFlags(&evE3,   cudaEventDisableTiming);
        init_done = true;
    }

    dim3 blk(256);
    cudaStream_t s0 = 0;

    // -------- input conversions needed by QKV (on s0) --------
    esplit_kernel<<<(Tt*Dm/4 + 255)/256, blk, 0, s0>>>(x, xh, xl, Tt*Dm);
    wsplit_t_kernel<<<dim3(Dm/32, Dm/32, 1), blk, 0, s0>>>(Wq, wqh, wql, Dm, Dm);
    wsplit_t_kernel<<<dim3(Dm/32, Dm/32, 1), blk, 0, s0>>>(Wk, wkh, wkl, Dm, Dm);
    wsplit_t_kernel<<<dim3(Dm/32, Dm/32, 1), blk, 0, s0>>>(Wv, wvh, wvl, Dm, Dm);
    wsplit_t_kernel<<<dim3(Dm/32, Dm/32, 1), blk, 0, s0>>>(Wo, woh, wol, Dm, Dm);

    // fork: st2 and st3 join after input conversions
    cudaEventRecord(evFork, s0);
    cudaStreamWaitEvent(st2, evFork, 0);
    cudaStreamWaitEvent(st3, evFork, 0);

    // -------- QKV projections, concurrent on 3 streams --------
    gemm_s<0,1><<<dim3(Dm/128, Tt/128), blk, SMEM_G, s0>>>(xh, xl, wqh, wql, bq, nullptr, qh, ql, Dm, Dm);
    gemm_s<0,1><<<dim3(Dm/128, Tt/128), blk, SMEM_G, st2>>>(xh, xl, wkh, wkl, bk, nullptr, kh, kl, Dm, Dm);
    cudaEventRecord(evK, st2);
    gemm_s<0,0><<<dim3(Dm/128, Tt/128), blk, SMEM_G, st3>>>(xh, xl, wvh, wvl, bv, pv, nullptr, nullptr, Dm, Dm);
    // vT transpose stays on st3 (program-ordered after V GEMM); runs
    // concurrently with scores_s on s0, which doesn't need V.
    wsplit_t_kernel<<<dim3(Dm/32, Ls/32, Bb), blk, 0, st3>>>(pv, vth, vtl, Ls, Dm);
    cudaEventRecord(evVT, st3);

    // st2 (after K): convert gate/gen/expert weight planes, hidden under attention
    wsplit_t_kernel<<<dim3(Dm/32, Dm/32, 1), blk, 0, st2>>>(gW1, gw1h, gw1l, Dm, Dm);
    wsplit_t_kernel<<<dim3(Fd/32, Dm/32, 1), blk, 0, st2>>>(geW1, gew1h, gew1l, Dm, Fd);
    wsplit_t_kernel<<<dim3(Dm/32, Fd/32, 1), blk, 0, st2>>>(geW2, gew2h, gew2l, Fd, Dm);
    wsplit_t_kernel<<<dim3(Fd/32, Dm/32, Ee), blk, 0, st2>>>(eW1, ew1h, ew1l, Dm, Fd);
    wsplit_t_kernel<<<dim3(Dm/32, Fd/32, Ee), blk, 0, st2>>>(eW2, ew2h, ew2l, Fd, Dm);
    cudaEventRecord(evW, st2);

    // -------- attention (s0): scores needs only q (s0) + k (evK) --------
    cudaStreamWaitEvent(s0, evK, 0);
    scores_s<<<dim3(Ls/128, Ls/128, Bb*Hh), blk, SMEM_G, s0>>>(attn);
    softmax_kernel<<<Bb*Hh*Ls, blk, 0, s0>>>(attn);
    cudaStreamWaitEvent(s0, evVT, 0);
    attnv_s<<<dim3(1, Ls/128, Bb*Hh), blk, SMEM_V, s0>>>();
    gemm_s<0,0><<<dim3(Dm/128, Tt/128), blk, SMEM_G, s0>>>(ctxh, ctxl, woh, wol, bo, ptmp, nullptr, nullptr, Dm, Dm);
    add_ln_kernel<<<Tt, blk, 0, s0>>>(x, ptmp, ln1g, ln1b, px1);
    cudaEventRecord(evX1, s0);

    // -------- general expert on st2, overlapped with routing path ----------
    cudaStreamWaitEvent(st2, evX1, 0);
    gemm_s<1,1><<<dim3(Fd/128, Tt/128), blk, SMEM_G, st2>>>(x1h, x1l, gew1h, gew1l, geb1, nullptr, gnh, gnl, Fd, Dm);
    gemm_s<0,0><<<dim3(Dm/128, Tt/128), blk, SMEM_G, st2>>>(gnh, gnl, gew2h, gew2l, geb2, pgen, nullptr, nullptr, Dm, Fd);
    cudaEventRecord(evG, st2);

    // -------- gate + routing on s0 --------
    cudaStreamWaitEvent(s0, evW, 0);
    gemm_s<1,0><<<dim3(Dm/128, Tt/128), blk, SMEM_G, s0>>>(x1h, x1l, gw1h, gw1l, gb1, pgh, nullptr, nullptr, Dm, Dm);
    gate_logits_kernel<<<Tt/32, blk, 0, s0>>>(gW2, gb2);
    init_kernel<<<1, 32, 0, s0>>>(loss);
    topk_kernel<<<Tt/256, blk, 0, s0>>>();
    cudaEventRecord(evT, s0);

    // -------- routed experts: two batched halves on two streams -----------
    // expert entry sets are disjoint -> cross-half writes are race-free.
    cudaStreamWaitEvent(st3, evT, 0);
    expert_s<0><<<dim3(Fd/128, Tt/128, Ee/2), blk, SMEM_G, s0>>>(ew1h, ew1l, eb1, 0);
    expert_s<1><<<dim3(Dm/128, Tt/128, Ee/2), blk, SMEM_G, s0>>>(ew2h, ew2l, eb2, 0);
    expert_s<0><<<dim3(Fd/128, Tt/128, Ee/2), blk, SMEM_G, st3>>>(ew1h, ew1l, eb1, Ee/2);
    expert_s<1><<<dim3(Dm/128, Tt/128, Ee/2), blk, SMEM_G, st3>>>(ew2h, ew2l, eb2, Ee/2);
    cudaEventRecord(evE3, st3);

    // -------- join + combine + LN2 --------
    cudaStreamWaitEvent(s0, evE3, 0);
    cudaStreamWaitEvent(s0, evG, 0);
    final_ln_kernel<<<Tt, blk, 0, s0>>>(ln2g, ln2b, out);
}